// round 13
// baseline (speedup 1.0000x reference)
#include <cuda_runtime.h>
#include <cuda_fp16.h>
#include <math.h>
#include <stdint.h>

// ---------------- model dims ----------------
#define BB    16
#define SS    512
#define DD    256
#define HH    8
#define DHD   32
#define NLAY  2
#define NEXP  8
#define EHID  1024
#define NTOK  (BB*SS)   // 8192

// ---------------- scratch (static device globals) ---------------------------
__device__ float  g_h   [NTOK*DD];
__device__ __half g_hh  [NTOK*DD];
__device__ __half g_qh  [NTOK*DD];     // Q fp16, pre-scaled, [B][H][S][32]
__device__ __half g_kh  [NTOK*DD];     // K fp16, [B][H][S][32]
__device__ __half g_vth [NTOK*DD];     // V fp16 transposed, [B][H][32][S]
__device__ __half g_ctxh[NTOK*DD];
__device__ float  g_tmp [NTOK*DD];
__device__ __half g_h1h [NTOK*EHID];   // MoE hidden (fp16, permuted rows)
__device__ float  g_pe  [SS*DD];
__device__ int    g_pad [NTOK];
__device__ uint32_t g_pbits[NTOK/32];
__device__ int    g_eidx[NTOK];
__device__ float  g_ew  [NTOK];
__device__ int    g_cnt [NLAY*NEXP];
__device__ int    g_base[NEXP];
__device__ int    g_cursor[NEXP];
__device__ int    g_perm[NTOK];
__device__ float  g_pool[BB*8*DD];
__device__ int    g_pcnt[BB*8];
__device__ int    g_tiletab[80];
__device__ int    g_ntiles;

// fp16 weight buffer (converted once per launch)
#define IPH_OFF 0
#define IPH_SZ  (NLAY*3*DD*DD)
#define OPH_OFF (IPH_OFF + IPH_SZ)
#define OPH_SZ  (NLAY*DD*DD)
#define W1H_OFF (OPH_OFF + OPH_SZ)
#define W1H_SZ  (NLAY*NEXP*EHID*DD)
#define W2H_OFF (W1H_OFF + W1H_SZ)
#define W2H_SZ  (NLAY*NEXP*DD*EHID)
#define WH_TOTAL (W2H_OFF + W2H_SZ)
__device__ __half g_wh[WH_TOTAL];

// ---------------- helpers ----------------------------------------------------
__device__ __forceinline__ void mma_f16(float* d, uint32_t a0, uint32_t a1,
                                        uint32_t a2, uint32_t a3,
                                        uint32_t b0, uint32_t b1)
{
    asm volatile(
        "mma.sync.aligned.m16n8k16.row.col.f32.f16.f16.f32 "
        "{%0,%1,%2,%3}, {%4,%5,%6,%7}, {%8,%9}, {%0,%1,%2,%3};\n"
        : "+f"(d[0]), "+f"(d[1]), "+f"(d[2]), "+f"(d[3])
        : "r"(a0), "r"(a1), "r"(a2), "r"(a3), "r"(b0), "r"(b1));
}

__device__ __forceinline__ void ldm_x4(uint32_t& r0, uint32_t& r1,
                                       uint32_t& r2, uint32_t& r3, uint32_t addr)
{
    asm volatile("ldmatrix.sync.aligned.m8n8.x4.shared.b16 {%0,%1,%2,%3}, [%4];"
                 : "=r"(r0), "=r"(r1), "=r"(r2), "=r"(r3) : "r"(addr));
}

__device__ __forceinline__ float fexp(float x)
{
    x = fmaxf(x, -87.0f);
    const float L2E = 1.4426950408889634f;
    float t  = fmaf(x, L2E, 12582912.0f);
    int   ki = __float_as_int(t) - 0x4B400000;
    float kf = t - 12582912.0f;
    float r  = fmaf(x, L2E, -kf);
    float p  = 1.3333558146e-3f;
    p = fmaf(p, r, 9.6181291076e-3f);
    p = fmaf(p, r, 5.5504108664e-2f);
    p = fmaf(p, r, 2.4022650696e-1f);
    p = fmaf(p, r, 6.9314718056e-1f);
    p = fmaf(p, r, 1.0f);
    return p * __int_as_float((ki + 127) << 23);
}

__device__ __forceinline__ uint32_t packh2(float a, float b)
{
    __half2 h = __floats2half2_rn(a, b);
    return *(uint32_t*)&h;
}

__device__ __forceinline__ void cp16(uint32_t dst, const void* src)
{
    asm volatile("cp.async.ca.shared.global [%0], [%1], 16;\n"
                 :: "r"(dst), "l"(src));
}

// ---------------- fp16 pipelined 128x128 GEMM core, BK=32 --------------------
#define H2STR 40
#define H2BUF (128 * H2STR)

__device__ __forceinline__ void pipe16_mainloop(
    const __half* __restrict__ aptr,
    const __half* __restrict__ wptr,
    int K, __half* AsArr, __half* BsArr, float acc[4][4][4])
{
    int tid = threadIdx.x, lane = tid & 31, w = tid >> 5;
    int wm = w & 1, wn = w >> 1;
    int row = tid >> 1, seg = (tid & 1) * 16;

    uint32_t aBase = (uint32_t)__cvta_generic_to_shared(AsArr);
    uint32_t bBase = (uint32_t)__cvta_generic_to_shared(BsArr);
    uint32_t da = aBase + (row * H2STR + seg) * 2;
    uint32_t db = bBase + (row * H2STR + seg) * 2;
    const uint32_t BUFB = H2BUF * 2;

    int l7 = lane & 7, lg1 = (lane >> 3) & 1, lg2 = (lane >> 4) & 1;
    uint32_t offA[4], offB[2];
    #pragma unroll
    for (int mt = 0; mt < 4; mt++) {
        int ar = wm * 64 + mt * 16 + l7 + lg1 * 8;
        offA[mt] = aBase + (ar * H2STR + lg2 * 8) * 2;
    }
    #pragma unroll
    for (int p = 0; p < 2; p++) {
        int br = wn * 32 + (2 * p + lg2) * 8 + l7;
        offB[p] = bBase + (br * H2STR + lg1 * 8) * 2;
    }

    int KT = K / 32;

    cp16(da,      aptr);     cp16(da + 16, aptr + 8);
    cp16(db,      wptr);     cp16(db + 16, wptr + 8);
    asm volatile("cp.async.commit_group;\n");

    for (int kt = 0; kt < KT; kt++) {
        if (kt + 1 < KT) {
            uint32_t off = ((kt + 1) & 1) * BUFB;
            const __half* as = aptr + (kt + 1) * 32;
            const __half* ws = wptr + (kt + 1) * 32;
            cp16(da + off,      as);     cp16(da + off + 16, as + 8);
            cp16(db + off,      ws);     cp16(db + off + 16, ws + 8);
            asm volatile("cp.async.commit_group;\n");
            asm volatile("cp.async.wait_group 1;\n");
        } else {
            asm volatile("cp.async.wait_group 0;\n");
        }
        __syncthreads();

        uint32_t so = (kt & 1) * BUFB;

        #pragma unroll
        for (int kh = 0; kh < 2; kh++) {
            uint32_t ko = so + kh * 32;
            uint32_t afr[4][4], bfr[4][2];
            #pragma unroll
            for (int mt = 0; mt < 4; mt++)
                ldm_x4(afr[mt][0], afr[mt][1], afr[mt][2], afr[mt][3], offA[mt] + ko);
            ldm_x4(bfr[0][0], bfr[0][1], bfr[1][0], bfr[1][1], offB[0] + ko);
            ldm_x4(bfr[2][0], bfr[2][1], bfr[3][0], bfr[3][1], offB[1] + ko);

            #pragma unroll
            for (int mt = 0; mt < 4; mt++)
                #pragma unroll
                for (int nt = 0; nt < 4; nt++)
                    mma_f16(acc[mt][nt], afr[mt][0], afr[mt][1], afr[mt][2], afr[mt][3],
                            bfr[nt][0], bfr[nt][1]);
        }
        __syncthreads();
    }
}

// ---------------- fused weight conversion (fp32 -> fp16, one kernel) ---------
__global__ void f2h_all(const float* __restrict__ s0, const float* __restrict__ s1,
                        const float* __restrict__ s2, const float* __restrict__ s3)
{
    int i = blockIdx.x * 256 + threadIdx.x;
    if (i >= WH_TOTAL / 4) return;
    const float* src;
    int local;
    if (i < IPH_SZ / 4)                        { src = s0; local = i; }
    else if (i < (IPH_SZ + OPH_SZ) / 4)        { src = s1; local = i - IPH_SZ / 4; }
    else if (i < (IPH_SZ + OPH_SZ + W1H_SZ)/4) { src = s2; local = i - (IPH_SZ + OPH_SZ) / 4; }
    else                                       { src = s3; local = i - (IPH_SZ + OPH_SZ + W1H_SZ) / 4; }
    float4 v = ((const float4*)src)[local];
    ((__half2*)g_wh)[2 * i + 0] = __floats2half2_rn(v.x, v.y);
    ((__half2*)g_wh)[2 * i + 1] = __floats2half2_rn(v.z, v.w);
}

// ---------------- positional encoding (cheap FP64) + cnt zeroing -------------
__global__ void pe_kernel()
{
    int d = blockIdx.x, s = threadIdx.x;
    if (blockIdx.x == 0 && threadIdx.x < NLAY * NEXP) g_cnt[threadIdx.x] = 0;
    __shared__ double freq_sh;
    if (threadIdx.x == 0)
        freq_sh = exp(-(double)(d & ~1) * (log(10000.0) / (double)DD));
    __syncthreads();
    double arg = (double)s * freq_sh;
    const double TWOPI = 6.283185307179586476925286766559;
    double r = arg - TWOPI * rint(arg * (1.0 / TWOPI));
    float rf = (float)r;
    g_pe[s * DD + d] = (d & 1) ? cosf(rf) : sinf(rf);
}

// ---------------- embedding + pad mask (warp per token) ----------------------
__global__ void embed_kernel(const int* __restrict__ x, const float* __restrict__ emb)
{
    int lane = threadIdx.x & 31;
    int n = blockIdx.x * 8 + (threadIdx.x >> 5);
    int tok = x[n];
    int s = n & (SS - 1);

    const float* er = emb + (size_t)tok * DD;
    const float* pr = g_pe + s * DD;
    size_t base = (size_t)n * DD;

    float v[8];
    float sum = 0.f;
    #pragma unroll
    for (int j = 0; j < 8; j++) {
        int d = lane + 32 * j;
        v[j] = er[d] * 16.0f + pr[d];
        sum += v[j];
        g_h [base + d] = v[j];
        g_hh[base + d] = __float2half(v[j]);
    }
    #pragma unroll
    for (int o = 16; o > 0; o >>= 1) sum += __shfl_xor_sync(0xffffffffu, sum, o);
    if (lane == 0) g_pad[n] = (sum == 0.0f) ? 1 : 0;
}

// ---------------- pack pad bits (warp per 32 tokens) -------------------------
__global__ void pack_pad_kernel()
{
    int wi = blockIdx.x * 32 + (threadIdx.x >> 5);
    int lane = threadIdx.x & 31;
    uint32_t bal = __ballot_sync(0xffffffffu, g_pad[wi * 32 + lane] != 0);
    if (lane == 0) g_pbits[wi] = bal;
}

// ---------------- QKV GEMM (fp16) + fp16 split store -------------------------
__global__ __launch_bounds__(256)
void gemm_qkv16(const __half* __restrict__ A,
                const __half* __restrict__ W,
                const float* __restrict__ bias)
{
    __shared__ __align__(16) __half As[2 * H2BUF];
    __shared__ __align__(16) __half Bs[2 * H2BUF];

    int tid = threadIdx.x, lane = tid & 31, w = tid >> 5;
    int wm = w & 1, wn = w >> 1, g = lane >> 2, T = lane & 3;
    int m0 = blockIdx.y * 128, n0 = blockIdx.x * 128;
    int row = tid >> 1, seg = (tid & 1) * 16;

    const float inv = 0.17677669529663689f;

    float acc[4][4][4] = {};
    pipe16_mainloop(A + (size_t)(m0 + row) * DD + seg,
                    W + (size_t)(n0 + row) * DD + seg, DD, As, Bs, acc);

    #pragma unroll
    for (int mt = 0; mt < 4; mt++) {
        #pragma unroll
        for (int nt = 0; nt < 4; nt++) {
            int r0 = m0 + wm * 64 + mt * 16 + g;
            int c0 = n0 + wn * 32 + nt * 8 + 2 * T;
            int t = c0 >> 8, h = (c0 >> 5) & 7, d = c0 & 31;
            float bx = bias[c0], by = bias[c0 + 1];
            #pragma unroll
            for (int half = 0; half < 2; half++) {
                int rr = r0 + half * 8;
                int b = rr >> 9, s = rr & (SS - 1);
                int bh = b * HH + h;
                float v0 = acc[mt][nt][half * 2 + 0] + bx;
                float v1 = acc[mt][nt][half * 2 + 1] + by;
                if (t == 0) {
                    *(uint32_t*)(g_qh + ((size_t)(bh * SS + s)) * DHD + d) =
                        packh2(v0 * inv, v1 * inv);
                } else if (t == 1) {
                    *(uint32_t*)(g_kh + ((size_t)(bh * SS + s)) * DHD + d) =
                        packh2(v0, v1);
                } else {
                    g_vth[((size_t)(bh * DHD + d    )) * SS + s] = __float2half(v0);
                    g_vth[((size_t)(bh * DHD + d + 1)) * SS + s] = __float2half(v1);
                }
            }
        }
    }
}

// ---------------- out-proj GEMM (fp16) ---------------------------------------
__global__ __launch_bounds__(256)
void gemm_out16(const __half* __restrict__ A,
                const __half* __restrict__ W,
                const float* __restrict__ bias,
                float* __restrict__ C, int Nc, int K)
{
    __shared__ __align__(16) __half As[2 * H2BUF];
    __shared__ __align__(16) __half Bs[2 * H2BUF];

    int tid = threadIdx.x, lane = tid & 31, w = tid >> 5;
    int wm = w & 1, wn = w >> 1, g = lane >> 2, T = lane & 3;
    int m0 = blockIdx.y * 128, n0 = blockIdx.x * 128;
    int row = tid >> 1, seg = (tid & 1) * 16;

    float acc[4][4][4] = {};
    pipe16_mainloop(A + (size_t)(m0 + row) * K + seg,
                    W + (size_t)(n0 + row) * K + seg, K, As, Bs, acc);

    #pragma unroll
    for (int mt = 0; mt < 4; mt++) {
        #pragma unroll
        for (int nt = 0; nt < 4; nt++) {
            int r0 = m0 + wm * 64 + mt * 16 + g;
            int c0 = n0 + wn * 32 + nt * 8 + 2 * T;
            float bx = bias[c0], by = bias[c0 + 1];
            #pragma unroll
            for (int half = 0; half < 2; half++) {
                int rr = r0 + half * 8;
                float2 v = make_float2(acc[mt][nt][half * 2 + 0] + bx,
                                       acc[mt][nt][half * 2 + 1] + by);
                *(float2*)(C + (size_t)rr * Nc + c0) = v;
            }
        }
    }
}

// ---------------- MoE GEMM1 (fp16, work-queue grid) --------------------------
__global__ __launch_bounds__(256)
void moe_gemm1_16(const __half* __restrict__ w1, const float* __restrict__ b1,
                  const int* __restrict__ cnt_l)
{
    int y = blockIdx.y;
    if (y >= g_ntiles) return;
    int ent = g_tiletab[y];
    int e = ent >> 16, tile = ent & 0xFFFF;
    int cnt = cnt_l[e];
    int ebase = g_base[e];

    __shared__ __align__(16) __half As[2 * H2BUF];
    __shared__ __align__(16) __half Bs[2 * H2BUF];

    int tid = threadIdx.x, lane = tid & 31, w = tid >> 5;
    int wm = w & 1, wn = w >> 1, g = lane >> 2, T = lane & 3;
    int n0 = blockIdx.x * 128;
    int row = tid >> 1, seg = (tid & 1) * 16;

    int gr = tile * 128 + row;
    if (gr >= cnt) gr = cnt - 1;
    int token = g_perm[ebase + gr];

    float acc[4][4][4] = {};
    pipe16_mainloop(g_hh + (size_t)token * DD + seg,
                    w1 + (size_t)e * EHID * DD + (size_t)(n0 + row) * DD + seg,
                    DD, As, Bs, acc);

    #pragma unroll
    for (int mt = 0; mt < 4; mt++) {
        #pragma unroll
        for (int nt = 0; nt < 4; nt++) {
            int lr0 = wm * 64 + mt * 16 + g;
            int c0  = n0 + wn * 32 + nt * 8 + 2 * T;
            float bx = b1[e * EHID + c0], by = b1[e * EHID + c0 + 1];
            #pragma unroll
            for (int half = 0; half < 2; half++) {
                int grr = tile * 128 + lr0 + half * 8;
                if (grr < cnt) {
                    float v0 = fmaxf(acc[mt][nt][half * 2 + 0] + bx, 0.f);
                    float v1 = fmaxf(acc[mt][nt][half * 2 + 1] + by, 0.f);
                    *(uint32_t*)(g_h1h + (size_t)(ebase + grr) * EHID + c0) = packh2(v0, v1);
                }
            }
        }
    }
}

// ---------------- MoE GEMM2 (fp16, work-queue grid) --------------------------
__global__ __launch_bounds__(256)
void moe_gemm2_16(const __half* __restrict__ w2, const float* __restrict__ b2,
                  const int* __restrict__ cnt_l)
{
    int y = blockIdx.y;
    if (y >= g_ntiles) return;
    int ent = g_tiletab[y];
    int e = ent >> 16, tile = ent & 0xFFFF;
    int cnt = cnt_l[e];
    int ebase = g_base[e];

    __shared__ __align__(16) __half As[2 * H2BUF];
    __shared__ __align__(16) __half Bs[2 * H2BUF];

    int tid = threadIdx.x, lane = tid & 31, w = tid >> 5;
    int wm = w & 1, wn = w >> 1, g = lane >> 2, T = lane & 3;
    int n0 = blockIdx.x * 128;
    int row = tid >> 1, seg = (tid & 1) * 16;

    int gr = tile * 128 + row;
    if (gr >= cnt) gr = cnt - 1;

    float acc[4][4][4] = {};
    pipe16_mainloop(g_h1h + (size_t)(ebase + gr) * EHID + seg,
                    w2 + (size_t)e * DD * EHID + (size_t)(n0 + row) * EHID + seg,
                    EHID, As, Bs, acc);

    #pragma unroll
    for (int mt = 0; mt < 4; mt++) {
        #pragma unroll
        for (int nt = 0; nt < 4; nt++) {
            int lr0 = wm * 64 + mt * 16 + g;
            int c0  = n0 + wn * 32 + nt * 8 + 2 * T;
            float bx = b2[e * DD + c0], by = b2[e * DD + c0 + 1];
            #pragma unroll
            for (int half = 0; half < 2; half++) {
                int grr = tile * 128 + lr0 + half * 8;
                if (grr < cnt) {
                    int token = g_perm[ebase + grr];
                    float gwv = g_ew[token];
                    float2 v = make_float2(gwv * (acc[mt][nt][half * 2 + 0] + bx),
                                           gwv * (acc[mt][nt][half * 2 + 1] + by));
                    *(float2*)(g_tmp + (size_t)token * DD + c0) = v;
                }
            }
        }
    }
}

// ---------------- flash attention (fp16, KCH=128, bit-packed mask) -----------
#define QTILE 128
#define KCH   128
#define QH    40
#define VSTR  136

__global__ void attn_fa_kernel()
{
    __shared__ __align__(16) __half Qs [QTILE * QH];        // 10 KB
    __shared__ __align__(16) __half Ks [2][KCH * QH];       // 20 KB
    __shared__ __align__(16) __half Vts[2][DHD * VSTR];     // 17 KB

    int qt = blockIdx.x, h = blockIdx.y, b = blockIdx.z;
    int tid = threadIdx.x, lane = tid & 31, w = tid >> 5;
    int g = lane >> 2, T = lane & 3;
    int bh = b * HH + h;

    const __half* Qgh = g_qh  + ((size_t)(bh * SS + qt * QTILE)) * DHD;
    const __half* Kgh = g_kh  + ((size_t)(bh * SS)) * DHD;
    const __half* Vgh = g_vth + ((size_t)bh * DHD) * SS;

    // cp.async geometry: K chunk = 512 16B-units; V chunk = 512 16B-units
    int ku0 = tid, ku1 = tid + 256;
    int kr0 = ku0 >> 2, kc0 = (ku0 & 3) * 8;
    int kr1 = ku1 >> 2, kc1 = (ku1 & 3) * 8;
    int vd0 = ku0 >> 4, vc0 = (ku0 & 15) * 8;
    int vd1 = ku1 >> 4, vc1 = (ku1 & 15) * 8;

    // load Q tile
    for (int i = tid; i < 512; i += 256) {
        int row = i >> 2, c = (i & 3) * 8;
        *(uint4*)(Qs + row * QH + c) = *(const uint4*)(Qgh + row * DHD + c);
    }

    // prefetch chunk 0
    {
        cp16((uint32_t)__cvta_generic_to_shared(&Ks[0][kr0 * QH + kc0]),
             Kgh + (size_t)kr0 * DHD + kc0);
        cp16((uint32_t)__cvta_generic_to_shared(&Ks[0][kr1 * QH + kc1]),
             Kgh + (size_t)kr1 * DHD + kc1);
        cp16((uint32_t)__cvta_generic_to_shared(&Vts[0][vd0 * VSTR + vc0]),
             Vgh + (size_t)vd0 * SS + vc0);
        cp16((uint32_t)__cvta_generic_to_shared(&Vts[0][vd1 * VSTR + vc1]),
             Vgh + (size_t)vd1 * SS + vc1);
        asm volatile("cp.async.commit_group;\n");
    }

    float m_[2]  = {-1e30f, -1e30f};
    float sum_[2] = {0.f, 0.f};
    float o[4][4] = {};

    for (int kc = 0; kc < SS / KCH; kc++) {
        int buf = kc & 1;
        // mask words for this chunk (broadcast loads)
        uint32_t mw[4];
        #pragma unroll
        for (int j = 0; j < 4; j++) mw[j] = g_pbits[b * 16 + kc * 4 + j];

        if (kc + 1 < SS / KCH) {
            int nb = (kc + 1) & 1;
            cp16((uint32_t)__cvta_generic_to_shared(&Ks[nb][kr0 * QH + kc0]),
                 Kgh + (size_t)((kc + 1) * KCH + kr0) * DHD + kc0);
            cp16((uint32_t)__cvta_generic_to_shared(&Ks[nb][kr1 * QH + kc1]),
                 Kgh + (size_t)((kc + 1) * KCH + kr1) * DHD + kc1);
            cp16((uint32_t)__cvta_generic_to_shared(&Vts[nb][vd0 * VSTR + vc0]),
                 Vgh + (size_t)vd0 * SS + (kc + 1) * KCH + vc0);
            cp16((uint32_t)__cvta_generic_to_shared(&Vts[nb][vd1 * VSTR + vc1]),
                 Vgh + (size_t)vd1 * SS + (kc + 1) * KCH + vc1);
            asm volatile("cp.async.commit_group;\n");
            asm volatile("cp.async.wait_group 1;\n");
        } else {
            asm volatile("cp.async.wait_group 0;\n");
        }
        __syncthreads();

        // ---- S = Q K^T : 16 n-tiles x 2 k-steps ----
        float s[16][4];
        #pragma unroll
        for (int nt = 0; nt < 16; nt++)
            #pragma unroll
            for (int j = 0; j < 4; j++) s[nt][j] = 0.f;

        #pragma unroll
        for (int ks = 0; ks < 2; ks++) {
            int row = w * 16 + g, col = ks * 16 + 2 * T;
            uint32_t a0 = *(const uint32_t*)(Qs + row * QH + col);
            uint32_t a1 = *(const uint32_t*)(Qs + (row + 8) * QH + col);
            uint32_t a2 = *(const uint32_t*)(Qs + row * QH + col + 8);
            uint32_t a3 = *(const uint32_t*)(Qs + (row + 8) * QH + col + 8);
            #pragma unroll
            for (int nt = 0; nt < 16; nt++) {
                int kr = nt * 8 + g;
                uint32_t b0 = *(const uint32_t*)(&Ks[buf][kr * QH + col]);
                uint32_t b1 = *(const uint32_t*)(&Ks[buf][kr * QH + col + 8]);
                mma_f16(s[nt], a0, a1, a2, a3, b0, b1);
            }
        }

        // ---- masking via bit-packed pads (word index nt>>2 is compile-time) --
        #pragma unroll
        for (int nt = 0; nt < 16; nt++) {
            uint32_t wbits = mw[nt >> 2];
            int bit0 = (nt & 3) * 8 + 2 * T;
            if ((wbits >> bit0) & 1)       { s[nt][0] = -1e9f; s[nt][2] = -1e9f; }
            if ((wbits >> (bit0 + 1)) & 1) { s[nt][1] = -1e9f; s[nt][3] = -1e9f; }
        }

        // ---- online softmax ----
        #pragma unroll
        for (int half = 0; half < 2; half++) {
            float cmax = -1e30f;
            #pragma unroll
            for (int nt = 0; nt < 16; nt++)
                cmax = fmaxf(cmax, fmaxf(s[nt][2 * half], s[nt][2 * half + 1]));
            cmax = fmaxf(cmax, __shfl_xor_sync(0xffffffffu, cmax, 1));
            cmax = fmaxf(cmax, __shfl_xor_sync(0xffffffffu, cmax, 2));
            float mnew  = fmaxf(m_[half], cmax);
            float scale = fexp(m_[half] - mnew);
            m_[half] = mnew;
            float part = 0.f;
            #pragma unroll
            for (int nt = 0; nt < 16; nt++) {
                float p0 = fexp(s[nt][2 * half]     - mnew);
                float p1 = fexp(s[nt][2 * half + 1] - mnew);
                s[nt][2 * half] = p0; s[nt][2 * half + 1] = p1;
                part += p0 + p1;
            }
            part += __shfl_xor_sync(0xffffffffu, part, 1);
            part += __shfl_xor_sync(0xffffffffu, part, 2);
            sum_[half] = sum_[half] * scale + part;
            #pragma unroll
            for (int nt = 0; nt < 4; nt++) {
                o[nt][2 * half]     *= scale;
                o[nt][2 * half + 1] *= scale;
            }
        }

        // ---- O += P @ V : 8 k-tiles x 4 n-tiles ----
        #pragma unroll
        for (int kt = 0; kt < 8; kt++) {
            uint32_t a0 = packh2(s[2 * kt][0],     s[2 * kt][1]);
            uint32_t a1 = packh2(s[2 * kt][2],     s[2 * kt][3]);
            uint32_t a2 = packh2(s[2 * kt + 1][0], s[2 * kt + 1][1]);
            uint32_t a3 = packh2(s[2 * kt + 1][2], s[2 * kt + 1][3]);
            #pragma unroll
            for (int nt = 0; nt < 4; nt++) {
                const __half* vp = &Vts[buf][(nt * 8 + g) * VSTR + kt * 16 + 2 * T];
                uint32_t b0 = *(const uint32_t*)vp;
                uint32_t b1 = *(const uint32_t*)(vp + 8);
                mma_f16(o[nt], a0, a1, a2, a3, b0, b1);
            }
        }
        __syncthreads();
    }

    float i0 = 1.0f / sum_[0];
    float i1 = 1.0f / sum_[1];
    int q0 = qt * QTILE + w * 16 + g;
    #pragma unroll
    for (int nt = 0; nt < 4; nt++) {
        int col = h * DHD + nt * 8 + 2 * T;
        *(uint32_t*)(g_ctxh + (size_t)(b * SS + q0) * DD + col) =
            packh2(o[nt][0] * i0, o[nt][1] * i0);
        *(uint32_t*)(g_ctxh + (size_t)(b * SS + q0 + 8) * DD + col) =
            packh2(o[nt][2] * i1, o[nt][3] * i1);
    }
}

// ---------------- fused residual + LN (+optional gate) -----------------------
__device__ __forceinline__ void warp_add_ln(
    int n, int lane, const float* __restrict__ add,
    const float* __restrict__ gamma, const float* __restrict__ beta,
    float out[8])
{
    size_t base = (size_t)n * DD + lane;
    float v[8];
    float sum = 0.f;
    #pragma unroll
    for (int j = 0; j < 8; j++) {
        v[j] = g_h[base + 32 * j] + add[base + 32 * j];
        sum += v[j];
    }
    #pragma unroll
    for (int o = 16; o > 0; o >>= 1) sum += __shfl_xor_sync(0xffffffffu, sum, o);
    float mu = sum * (1.0f / DD);
    float sq = 0.f;
    #pragma unroll
    for (int j = 0; j < 8; j++) {
        v[j] -= mu;
        sq += v[j] * v[j];
    }
    #pragma unroll
    for (int o = 16; o > 0; o >>= 1) sq += __shfl_xor_sync(0xffffffffu, sq, o);
    float r = rsqrtf(sq * (1.0f / DD) + 1e-5f);
    #pragma unroll
    for (int j = 0; j < 8; j++) {
        out[j] = v[j] * r * gamma[lane + 32 * j] + beta[lane + 32 * j];
        g_h [base + 32 * j] = out[j];
        g_hh[base + 32 * j] = __float2half(out[j]);
    }
}

__global__ void add_ln2_kernel(const float* __restrict__ add,
                               const float* __restrict__ gamma,
                               const float* __restrict__ beta)
{
    int lane = threadIdx.x & 31;
    int n = blockIdx.x * 8 + (threadIdx.x >> 5);
    float out[8];
    warp_add_ln(n, lane, add, gamma, beta, out);
}

__global__ void add_ln1_gate_kernel(const float* __restrict__ add,
                                    const float* __restrict__ gamma,
                                    const float* __restrict__ beta,
                                    const float* __restrict__ gw,
                                    const float* __restrict__ gb,
                                    int* __restrict__ cnt_l)
{
    int lane = threadIdx.x & 31;
    int n = blockIdx.x * 8 + (threadIdx.x >> 5);
    float out[8];
    warp_add_ln(n, lane, add, gamma, beta, out);

    float lg[NEXP];
    #pragma unroll
    for (int e = 0; e < NEXP; e++) {
        float p = 0.f;
        #pragma unroll
        for (int j = 0; j < 8; j++)
            p = fmaf(gw[e * DD + lane + 32 * j], out[j], p);
        #pragma unroll
        for (int o = 16; o > 0; o >>= 1)
            p += __shfl_xor_sync(0xffffffffu, p, o);
        lg[e] = p;
    }
    if (lane == 0) {
        float m = -1e30f;
        #pragma unroll
        for (int i = 0; i < NEXP; i++) { lg[i] += gb[i]; m = fmaxf(m, lg[i]); }
        float p[NEXP], sum = 0.f;
        #pragma unroll
        for (int i = 0; i < NEXP; i++) { p[i] = expf(lg[i] - m); sum += p[i]; }
        int bi = 0; float bw = p[0];
        #pragma unroll
        for (int i = 1; i < NEXP; i++) if (p[i] > bw) { bw = p[i]; bi = i; }
        g_eidx[n] = bi;
        g_ew[n]   = bw / sum;
        atomicAdd(&cnt_l[bi], 1);
    }
}

// ---------------- routing bookkeeping (prefix + tile table) ------------------
__global__ void prefix_kernel(const int* __restrict__ cnt_l)
{
    if (threadIdx.x == 0) {
        int acc = 0, idx = 0;
        #pragma unroll
        for (int e = 0; e < NEXP; e++) {
            g_base[e] = acc; g_cursor[e] = acc;
            int c = cnt_l[e];
            acc += c;
            int nt = (c + 127) >> 7;
            for (int t = 0; t < nt; t++) g_tiletab[idx++] = (e << 16) | t;
        }
        g_ntiles = idx;
    }
}

__global__ void scatter_kernel()
{
    int n = blockIdx.x * blockDim.x + threadIdx.x;
    if (n < NTOK) {
        int e = g_eidx[n];
        int pos = atomicAdd(&g_cursor[e], 1);
        g_perm[pos] = n;
    }
}

// ---------------- head: partial pooling + final ------------------------------
__global__ void pool_kernel()
{
    int b = blockIdx.x, c = blockIdx.y;
    int tid = threadIdx.x;
    int base = b * SS + c * 64;
    float s = 0.f;
    #pragma unroll 8
    for (int i = 0; i < 64; i++) {
        int n = base + i;
        if (!g_pad[n]) s += g_h[(size_t)n * DD + tid];
    }
    g_pool[(b * 8 + c) * DD + tid] = s;
    if (tid == 0) {
        int t = 0;
        #pragma unroll 8
        for (int i = 0; i < 64; i++) t += (g_pad[base + i] == 0);
        g_pcnt[b * 8 + c] = t;
    }
}

__global__ void head_final(const float* __restrict__ fc1w, const float* __restrict__ fc1b,
                           const float* __restrict__ fc2w, const float* __restrict__ fc2b,
                           float* __restrict__ out)
{
    int b = blockIdx.x, tid = threadIdx.x;
    __shared__ float pooled[DD];
    __shared__ float z[128];
    __shared__ int scnt;

    float s = 0.f;
    #pragma unroll
    for (int c = 0; c < 8; c++) s += g_pool[(b * 8 + c) * DD + tid];
    if (tid == 0) {
        int t = 0;
        #pragma unroll
        for (int c = 0; c < 8; c++) t += g_pcnt[b * 8 + c];
        scnt = t;
    }
    __syncthreads();
    pooled[tid] = s / fmaxf((float)scnt, 1.0f);
    __syncthreads();

    if (tid < 128) {
        float a = fc1b[tid];
        const float* wr = fc1w + (size_t)tid * DD;
        #pragma unroll 8
        for (int d = 0; d < DD; d++) a += pooled[d] * wr[d];
        z[tid] = fmaxf(a, 0.f);
    }
    __syncthreads();
    if (tid < 2) {
        float a = fc2b[tid];
        const float* wr = fc2w + (size_t)tid * 128;
        #pragma unroll 8
        for (int i = 0; i < 128; i++) a += z[i] * wr[i];
        out[b * 2 + tid] = a;
    }
}

// ---------------- host launch ------------------------------------------------
static void* sym_addr(const void* sym)
{
    void* p = nullptr;
    cudaGetSymbolAddress(&p, sym);
    return p;
}

extern "C" void kernel_launch(void* const* d_in, const int* in_sizes, int n_in,
                              void* d_out, int out_size)
{
    const int*   x          = (const int*)  d_in[0];
    const float* emb        = (const float*)d_in[1];
    const float* in_proj_w  = (const float*)d_in[2];
    const float* in_proj_b  = (const float*)d_in[3];
    const float* out_proj_w = (const float*)d_in[4];
    const float* out_proj_b = (const float*)d_in[5];
    const float* ln1_g      = (const float*)d_in[6];
    const float* ln1_b      = (const float*)d_in[7];
    const float* ln2_g      = (const float*)d_in[8];
    const float* ln2_b      = (const float*)d_in[9];
    const float* gate_w     = (const float*)d_in[10];
    const float* gate_b     = (const float*)d_in[11];
    const float* w1         = (const float*)d_in[12];
    const float* b1         = (const float*)d_in[13];
    const float* w2         = (const float*)d_in[14];
    const float* b2         = (const float*)d_in[15];
    const float* fc1_w      = (const float*)d_in[16];
    const float* fc1_b      = (const float*)d_in[17];
    const float* fc2_w      = (const float*)d_in[18];
    const float* fc2_b      = (const float*)d_in[19];
    float* out = (float*)d_out;

    __half* wh    = (__half*)sym_addr(g_wh);
    __half* hh    = (__half*)sym_addr(g_hh);
    __half* ctxh  = (__half*)sym_addr(g_ctxh);
    float*  p_tmp = (float*)sym_addr(g_tmp);
    int*    cnt   = (int*)sym_addr(g_cnt);

    pe_kernel<<<DD, SS>>>();
    embed_kernel<<<NTOK/8, 256>>>(x, emb);
    pack_pad_kernel<<<8, 1024>>>();
    f2h_all<<<(WH_TOTAL/4 + 255)/256, 256>>>(in_proj_w, out_proj_w, w1, w2);

    for (int l = 0; l < NLAY; l++) {
        int* cnt_l = cnt + l * NEXP;

        gemm_qkv16<<<dim3(3*DD/128, NTOK/128), 256>>>(
            hh, wh + IPH_OFF + (size_t)l * 3*DD*DD, in_proj_b + (size_t)l * 3*DD);

        attn_fa_kernel<<<dim3(SS/QTILE, HH, BB), 256>>>();

        gemm_out16<<<dim3(DD/128, NTOK/128), 256>>>(
            ctxh, wh + OPH_OFF + (size_t)l * DD*DD, out_proj_b + (size_t)l * DD,
            p_tmp, DD, DD);

        add_ln1_gate_kernel<<<NTOK/8, 256>>>(
            p_tmp, ln1_g + (size_t)l * DD, ln1_b + (size_t)l * DD,
            gate_w + (size_t)l * NEXP*DD, gate_b + (size_t)l * NEXP, cnt_l);
        prefix_kernel<<<1, 32>>>(cnt_l);
        scatter_kernel<<<NTOK/256, 256>>>();

        moe_gemm1_16<<<dim3(EHID/128, 71), 256>>>(
            wh + W1H_OFF + (size_t)l * NEXP*EHID*DD, b1 + (size_t)l * NEXP*EHID, cnt_l);
        moe_gemm2_16<<<dim3(DD/128, 71), 256>>>(
            wh + W2H_OFF + (size_t)l * NEXP*DD*EHID, b2 + (size_t)l * NEXP*DD, cnt_l);

        add_ln2_kernel<<<NTOK/8, 256>>>(
            p_tmp, ln2_g + (size_t)l * DD, ln2_b + (size_t)l * DD);
    }

    pool_kernel<<<dim3(BB, 8), 256>>>();
    head_final<<<BB, 256>>>(fc1_w, fc1_b, fc2_w, fc2_b, out);
}

// round 15
// speedup vs baseline: 1.5122x; 1.5122x over previous
#include <cuda_runtime.h>
#include <cuda_fp16.h>
#include <math.h>
#include <stdint.h>

// ---------------- model dims ----------------
#define BB    16
#define SS    512
#define DD    256
#define HH    8
#define DHD   32
#define NLAY  2
#define NEXP  8
#define EHID  1024
#define NTOK  (BB*SS)   // 8192

// ---------------- scratch (static device globals) ---------------------------
__device__ float  g_h   [NTOK*DD];
__device__ __half g_hh  [NTOK*DD];
__device__ __half g_qh  [NTOK*DD];     // Q fp16, pre-scaled, [B][H][S][32]
__device__ __half g_kh  [NTOK*DD];     // K fp16, [B][H][S][32]
__device__ __half g_vth [NTOK*DD];     // V fp16 transposed, [B][H][32][S]
__device__ __half g_ctxh[NTOK*DD];
__device__ float  g_tmp [NTOK*DD];
__device__ __half g_h1h [NTOK*EHID];   // MoE hidden (fp16, permuted rows)
__device__ float  g_pe  [SS*DD];
__device__ int    g_pad [NTOK];
__device__ uint32_t g_pbits[NTOK/32];
__device__ int    g_eidx[NTOK];
__device__ float  g_ew  [NTOK];
__device__ int    g_cnt [NLAY*NEXP];
__device__ int    g_base[NEXP];
__device__ int    g_cursor[NEXP];
__device__ int    g_perm[NTOK];
__device__ float  g_pool[BB*8*DD];
__device__ int    g_pcnt[BB*8];
__device__ int    g_tiletab[80];
__device__ int    g_ntiles;

// fp16 weight buffer (converted once per launch)
#define IPH_OFF 0
#define IPH_SZ  (NLAY*3*DD*DD)
#define OPH_OFF (IPH_OFF + IPH_SZ)
#define OPH_SZ  (NLAY*DD*DD)
#define W1H_OFF (OPH_OFF + OPH_SZ)
#define W1H_SZ  (NLAY*NEXP*EHID*DD)
#define W2H_OFF (W1H_OFF + W1H_SZ)
#define W2H_SZ  (NLAY*NEXP*DD*EHID)
#define WH_TOTAL (W2H_OFF + W2H_SZ)
__device__ __half g_wh[WH_TOTAL];

// ---------------- helpers ----------------------------------------------------
__device__ __forceinline__ void mma_f16(float* d, uint32_t a0, uint32_t a1,
                                        uint32_t a2, uint32_t a3,
                                        uint32_t b0, uint32_t b1)
{
    asm volatile(
        "mma.sync.aligned.m16n8k16.row.col.f32.f16.f16.f32 "
        "{%0,%1,%2,%3}, {%4,%5,%6,%7}, {%8,%9}, {%0,%1,%2,%3};\n"
        : "+f"(d[0]), "+f"(d[1]), "+f"(d[2]), "+f"(d[3])
        : "r"(a0), "r"(a1), "r"(a2), "r"(a3), "r"(b0), "r"(b1));
}

__device__ __forceinline__ void ldm_x4(uint32_t& r0, uint32_t& r1,
                                       uint32_t& r2, uint32_t& r3, uint32_t addr)
{
    asm volatile("ldmatrix.sync.aligned.m8n8.x4.shared.b16 {%0,%1,%2,%3}, [%4];"
                 : "=r"(r0), "=r"(r1), "=r"(r2), "=r"(r3) : "r"(addr));
}

__device__ __forceinline__ float fexp(float x)
{
    x = fmaxf(x, -87.0f);
    const float L2E = 1.4426950408889634f;
    float t  = fmaf(x, L2E, 12582912.0f);
    int   ki = __float_as_int(t) - 0x4B400000;
    float kf = t - 12582912.0f;
    float r  = fmaf(x, L2E, -kf);
    float p  = 1.3333558146e-3f;
    p = fmaf(p, r, 9.6181291076e-3f);
    p = fmaf(p, r, 5.5504108664e-2f);
    p = fmaf(p, r, 2.4022650696e-1f);
    p = fmaf(p, r, 6.9314718056e-1f);
    p = fmaf(p, r, 1.0f);
    return p * __int_as_float((ki + 127) << 23);
}

__device__ __forceinline__ uint32_t packh2(float a, float b)
{
    __half2 h = __floats2half2_rn(a, b);
    return *(uint32_t*)&h;
}

__device__ __forceinline__ void cp16(uint32_t dst, const void* src)
{
    asm volatile("cp.async.ca.shared.global [%0], [%1], 16;\n"
                 :: "r"(dst), "l"(src));
}

// ---------------- fp16 pipelined 128x128 GEMM core, BK=32 --------------------
#define H2STR 40
#define H2BUF (128 * H2STR)

__device__ __forceinline__ void pipe16_mainloop(
    const __half* __restrict__ aptr,
    const __half* __restrict__ wptr,
    int K, __half* AsArr, __half* BsArr, float acc[4][4][4])
{
    int tid = threadIdx.x, lane = tid & 31, w = tid >> 5;
    int wm = w & 1, wn = w >> 1;
    int row = tid >> 1, seg = (tid & 1) * 16;

    uint32_t aBase = (uint32_t)__cvta_generic_to_shared(AsArr);
    uint32_t bBase = (uint32_t)__cvta_generic_to_shared(BsArr);
    uint32_t da = aBase + (row * H2STR + seg) * 2;
    uint32_t db = bBase + (row * H2STR + seg) * 2;
    const uint32_t BUFB = H2BUF * 2;

    int l7 = lane & 7, lg1 = (lane >> 3) & 1, lg2 = (lane >> 4) & 1;
    uint32_t offA[4], offB[2];
    #pragma unroll
    for (int mt = 0; mt < 4; mt++) {
        int ar = wm * 64 + mt * 16 + l7 + lg1 * 8;
        offA[mt] = aBase + (ar * H2STR + lg2 * 8) * 2;
    }
    #pragma unroll
    for (int p = 0; p < 2; p++) {
        int br = wn * 32 + (2 * p + lg2) * 8 + l7;
        offB[p] = bBase + (br * H2STR + lg1 * 8) * 2;
    }

    int KT = K / 32;

    cp16(da,      aptr);     cp16(da + 16, aptr + 8);
    cp16(db,      wptr);     cp16(db + 16, wptr + 8);
    asm volatile("cp.async.commit_group;\n");

    for (int kt = 0; kt < KT; kt++) {
        if (kt + 1 < KT) {
            uint32_t off = ((kt + 1) & 1) * BUFB;
            const __half* as = aptr + (kt + 1) * 32;
            const __half* ws = wptr + (kt + 1) * 32;
            cp16(da + off,      as);     cp16(da + off + 16, as + 8);
            cp16(db + off,      ws);     cp16(db + off + 16, ws + 8);
            asm volatile("cp.async.commit_group;\n");
            asm volatile("cp.async.wait_group 1;\n");
        } else {
            asm volatile("cp.async.wait_group 0;\n");
        }
        __syncthreads();

        uint32_t so = (kt & 1) * BUFB;

        #pragma unroll
        for (int kh = 0; kh < 2; kh++) {
            uint32_t ko = so + kh * 32;
            uint32_t afr[4][4], bfr[4][2];
            #pragma unroll
            for (int mt = 0; mt < 4; mt++)
                ldm_x4(afr[mt][0], afr[mt][1], afr[mt][2], afr[mt][3], offA[mt] + ko);
            ldm_x4(bfr[0][0], bfr[0][1], bfr[1][0], bfr[1][1], offB[0] + ko);
            ldm_x4(bfr[2][0], bfr[2][1], bfr[3][0], bfr[3][1], offB[1] + ko);

            #pragma unroll
            for (int mt = 0; mt < 4; mt++)
                #pragma unroll
                for (int nt = 0; nt < 4; nt++)
                    mma_f16(acc[mt][nt], afr[mt][0], afr[mt][1], afr[mt][2], afr[mt][3],
                            bfr[nt][0], bfr[nt][1]);
        }
        __syncthreads();
    }
}

// ---------------- fused weight conversion (fp32 -> fp16, one kernel) ---------
__global__ void f2h_all(const float* __restrict__ s0, const float* __restrict__ s1,
                        const float* __restrict__ s2, const float* __restrict__ s3)
{
    int i = blockIdx.x * 256 + threadIdx.x;
    if (i >= WH_TOTAL / 4) return;
    const float* src;
    int local;
    if (i < IPH_SZ / 4)                        { src = s0; local = i; }
    else if (i < (IPH_SZ + OPH_SZ) / 4)        { src = s1; local = i - IPH_SZ / 4; }
    else if (i < (IPH_SZ + OPH_SZ + W1H_SZ)/4) { src = s2; local = i - (IPH_SZ + OPH_SZ) / 4; }
    else                                       { src = s3; local = i - (IPH_SZ + OPH_SZ + W1H_SZ) / 4; }
    float4 v = ((const float4*)src)[local];
    ((__half2*)g_wh)[2 * i + 0] = __floats2half2_rn(v.x, v.y);
    ((__half2*)g_wh)[2 * i + 1] = __floats2half2_rn(v.z, v.w);
}

// ---------------- positional encoding (cheap FP64) + cnt zeroing -------------
__global__ void pe_kernel()
{
    int d = blockIdx.x, s = threadIdx.x;
    if (blockIdx.x == 0 && threadIdx.x < NLAY * NEXP) g_cnt[threadIdx.x] = 0;
    __shared__ double freq_sh;
    if (threadIdx.x == 0)
        freq_sh = exp(-(double)(d & ~1) * (log(10000.0) / (double)DD));
    __syncthreads();
    double arg = (double)s * freq_sh;
    const double TWOPI = 6.283185307179586476925286766559;
    double r = arg - TWOPI * rint(arg * (1.0 / TWOPI));
    float rf = (float)r;
    g_pe[s * DD + d] = (d & 1) ? cosf(rf) : sinf(rf);
}

// ---------------- embedding + pad mask (warp per token) ----------------------
__global__ void embed_kernel(const int* __restrict__ x, const float* __restrict__ emb)
{
    int lane = threadIdx.x & 31;
    int n = blockIdx.x * 8 + (threadIdx.x >> 5);
    int tok = x[n];
    int s = n & (SS - 1);

    const float* er = emb + (size_t)tok * DD;
    const float* pr = g_pe + s * DD;
    size_t base = (size_t)n * DD;

    float v[8];
    float sum = 0.f;
    #pragma unroll
    for (int j = 0; j < 8; j++) {
        int d = lane + 32 * j;
        v[j] = er[d] * 16.0f + pr[d];
        sum += v[j];
        g_h [base + d] = v[j];
        g_hh[base + d] = __float2half(v[j]);
    }
    #pragma unroll
    for (int o = 16; o > 0; o >>= 1) sum += __shfl_xor_sync(0xffffffffu, sum, o);
    if (lane == 0) g_pad[n] = (sum == 0.0f) ? 1 : 0;
}

// ---------------- pack pad bits (warp per 32 tokens) -------------------------
__global__ void pack_pad_kernel()
{
    int wi = blockIdx.x * 32 + (threadIdx.x >> 5);
    int lane = threadIdx.x & 31;
    uint32_t bal = __ballot_sync(0xffffffffu, g_pad[wi * 32 + lane] != 0);
    if (lane == 0) g_pbits[wi] = bal;
}

// ---------------- QKV GEMM (fp16) + fp16 split store -------------------------
__global__ __launch_bounds__(256)
void gemm_qkv16(const __half* __restrict__ A,
                const __half* __restrict__ W,
                const float* __restrict__ bias)
{
    __shared__ __align__(16) __half As[2 * H2BUF];
    __shared__ __align__(16) __half Bs[2 * H2BUF];

    int tid = threadIdx.x, lane = tid & 31, w = tid >> 5;
    int wm = w & 1, wn = w >> 1, g = lane >> 2, T = lane & 3;
    int m0 = blockIdx.y * 128, n0 = blockIdx.x * 128;
    int row = tid >> 1, seg = (tid & 1) * 16;

    const float inv = 0.17677669529663689f;

    float acc[4][4][4] = {};
    pipe16_mainloop(A + (size_t)(m0 + row) * DD + seg,
                    W + (size_t)(n0 + row) * DD + seg, DD, As, Bs, acc);

    #pragma unroll
    for (int mt = 0; mt < 4; mt++) {
        #pragma unroll
        for (int nt = 0; nt < 4; nt++) {
            int r0 = m0 + wm * 64 + mt * 16 + g;
            int c0 = n0 + wn * 32 + nt * 8 + 2 * T;
            int t = c0 >> 8, h = (c0 >> 5) & 7, d = c0 & 31;
            float bx = bias[c0], by = bias[c0 + 1];
            #pragma unroll
            for (int half = 0; half < 2; half++) {
                int rr = r0 + half * 8;
                int b = rr >> 9, s = rr & (SS - 1);
                int bh = b * HH + h;
                float v0 = acc[mt][nt][half * 2 + 0] + bx;
                float v1 = acc[mt][nt][half * 2 + 1] + by;
                if (t == 0) {
                    *(uint32_t*)(g_qh + ((size_t)(bh * SS + s)) * DHD + d) =
                        packh2(v0 * inv, v1 * inv);
                } else if (t == 1) {
                    *(uint32_t*)(g_kh + ((size_t)(bh * SS + s)) * DHD + d) =
                        packh2(v0, v1);
                } else {
                    g_vth[((size_t)(bh * DHD + d    )) * SS + s] = __float2half(v0);
                    g_vth[((size_t)(bh * DHD + d + 1)) * SS + s] = __float2half(v1);
                }
            }
        }
    }
}

// ---------------- out-proj GEMM (fp16) ---------------------------------------
__global__ __launch_bounds__(256)
void gemm_out16(const __half* __restrict__ A,
                const __half* __restrict__ W,
                const float* __restrict__ bias,
                float* __restrict__ C, int Nc, int K)
{
    __shared__ __align__(16) __half As[2 * H2BUF];
    __shared__ __align__(16) __half Bs[2 * H2BUF];

    int tid = threadIdx.x, lane = tid & 31, w = tid >> 5;
    int wm = w & 1, wn = w >> 1, g = lane >> 2, T = lane & 3;
    int m0 = blockIdx.y * 128, n0 = blockIdx.x * 128;
    int row = tid >> 1, seg = (tid & 1) * 16;

    float acc[4][4][4] = {};
    pipe16_mainloop(A + (size_t)(m0 + row) * K + seg,
                    W + (size_t)(n0 + row) * K + seg, K, As, Bs, acc);

    #pragma unroll
    for (int mt = 0; mt < 4; mt++) {
        #pragma unroll
        for (int nt = 0; nt < 4; nt++) {
            int r0 = m0 + wm * 64 + mt * 16 + g;
            int c0 = n0 + wn * 32 + nt * 8 + 2 * T;
            float bx = bias[c0], by = bias[c0 + 1];
            #pragma unroll
            for (int half = 0; half < 2; half++) {
                int rr = r0 + half * 8;
                float2 v = make_float2(acc[mt][nt][half * 2 + 0] + bx,
                                       acc[mt][nt][half * 2 + 1] + by);
                *(float2*)(C + (size_t)rr * Nc + c0) = v;
            }
        }
    }
}

// ---------------- MoE GEMM1 (fp16, work-queue grid) --------------------------
__global__ __launch_bounds__(256)
void moe_gemm1_16(const __half* __restrict__ w1, const float* __restrict__ b1,
                  const int* __restrict__ cnt_l)
{
    int y = blockIdx.y;
    if (y >= g_ntiles) return;
    int ent = g_tiletab[y];
    int e = ent >> 16, tile = ent & 0xFFFF;
    int cnt = cnt_l[e];
    int ebase = g_base[e];

    __shared__ __align__(16) __half As[2 * H2BUF];
    __shared__ __align__(16) __half Bs[2 * H2BUF];

    int tid = threadIdx.x, lane = tid & 31, w = tid >> 5;
    int wm = w & 1, wn = w >> 1, g = lane >> 2, T = lane & 3;
    int n0 = blockIdx.x * 128;
    int row = tid >> 1, seg = (tid & 1) * 16;

    int gr = tile * 128 + row;
    if (gr >= cnt) gr = cnt - 1;
    int token = g_perm[ebase + gr];

    float acc[4][4][4] = {};
    pipe16_mainloop(g_hh + (size_t)token * DD + seg,
                    w1 + (size_t)e * EHID * DD + (size_t)(n0 + row) * DD + seg,
                    DD, As, Bs, acc);

    #pragma unroll
    for (int mt = 0; mt < 4; mt++) {
        #pragma unroll
        for (int nt = 0; nt < 4; nt++) {
            int lr0 = wm * 64 + mt * 16 + g;
            int c0  = n0 + wn * 32 + nt * 8 + 2 * T;
            float bx = b1[e * EHID + c0], by = b1[e * EHID + c0 + 1];
            #pragma unroll
            for (int half = 0; half < 2; half++) {
                int grr = tile * 128 + lr0 + half * 8;
                if (grr < cnt) {
                    float v0 = fmaxf(acc[mt][nt][half * 2 + 0] + bx, 0.f);
                    float v1 = fmaxf(acc[mt][nt][half * 2 + 1] + by, 0.f);
                    *(uint32_t*)(g_h1h + (size_t)(ebase + grr) * EHID + c0) = packh2(v0, v1);
                }
            }
        }
    }
}

// ---------------- MoE GEMM2 (fp16, work-queue grid) --------------------------
__global__ __launch_bounds__(256)
void moe_gemm2_16(const __half* __restrict__ w2, const float* __restrict__ b2,
                  const int* __restrict__ cnt_l)
{
    int y = blockIdx.y;
    if (y >= g_ntiles) return;
    int ent = g_tiletab[y];
    int e = ent >> 16, tile = ent & 0xFFFF;
    int cnt = cnt_l[e];
    int ebase = g_base[e];

    __shared__ __align__(16) __half As[2 * H2BUF];
    __shared__ __align__(16) __half Bs[2 * H2BUF];

    int tid = threadIdx.x, lane = tid & 31, w = tid >> 5;
    int wm = w & 1, wn = w >> 1, g = lane >> 2, T = lane & 3;
    int n0 = blockIdx.x * 128;
    int row = tid >> 1, seg = (tid & 1) * 16;

    int gr = tile * 128 + row;
    if (gr >= cnt) gr = cnt - 1;

    float acc[4][4][4] = {};
    pipe16_mainloop(g_h1h + (size_t)(ebase + gr) * EHID + seg,
                    w2 + (size_t)e * DD * EHID + (size_t)(n0 + row) * EHID + seg,
                    EHID, As, Bs, acc);

    #pragma unroll
    for (int mt = 0; mt < 4; mt++) {
        #pragma unroll
        for (int nt = 0; nt < 4; nt++) {
            int lr0 = wm * 64 + mt * 16 + g;
            int c0  = n0 + wn * 32 + nt * 8 + 2 * T;
            float bx = b2[e * DD + c0], by = b2[e * DD + c0 + 1];
            #pragma unroll
            for (int half = 0; half < 2; half++) {
                int grr = tile * 128 + lr0 + half * 8;
                if (grr < cnt) {
                    int token = g_perm[ebase + grr];
                    float gwv = g_ew[token];
                    float2 v = make_float2(gwv * (acc[mt][nt][half * 2 + 0] + bx),
                                           gwv * (acc[mt][nt][half * 2 + 1] + by));
                    *(float2*)(g_tmp + (size_t)token * DD + c0) = v;
                }
            }
        }
    }
}

// ---------------- flash attention (fp16, KCH=64, bit-packed mask) ------------
#define QTILE 128
#define KCH   64
#define QH    40
#define VSTR  72

__global__ void attn_fa_kernel()
{
    __shared__ __align__(16) __half Qs [QTILE * QH];
    __shared__ __align__(16) __half Ks [2][KCH * QH];
    __shared__ __align__(16) __half Vts[2][DHD * VSTR];

    int qt = blockIdx.x, h = blockIdx.y, b = blockIdx.z;
    int tid = threadIdx.x, lane = tid & 31, w = tid >> 5;
    int g = lane >> 2, T = lane & 3;
    int bh = b * HH + h;

    const __half* Qgh = g_qh  + ((size_t)(bh * SS + qt * QTILE)) * DHD;
    const __half* Kgh = g_kh  + ((size_t)(bh * SS)) * DHD;
    const __half* Vgh = g_vth + ((size_t)bh * DHD) * SS;

    int krow = tid >> 2, kcol = (tid & 3) * 8;
    int vd   = tid >> 3, vcol = (tid & 7) * 8;
    uint32_t ksd[2], vsd[2];
    #pragma unroll
    for (int p = 0; p < 2; p++) {
        ksd[p] = (uint32_t)__cvta_generic_to_shared(&Ks[p][krow * QH + kcol]);
        vsd[p] = (uint32_t)__cvta_generic_to_shared(&Vts[p][vd * VSTR + vcol]);
    }

    for (int i = tid; i < 512; i += 256) {
        int row = i >> 2, c = (i & 3) * 8;
        *(uint4*)(Qs + row * QH + c) = *(const uint4*)(Qgh + row * DHD + c);
    }

    {
        cp16(ksd[0], Kgh + (size_t)krow * DHD + kcol);
        cp16(vsd[0], Vgh + (size_t)vd * SS + vcol);
        asm volatile("cp.async.commit_group;\n");
    }

    float m_[2]  = {-1e30f, -1e30f};
    float sum_[2] = {0.f, 0.f};
    float o[4][4] = {};

    for (int kc = 0; kc < SS / KCH; kc++) {
        int buf = kc & 1;
        // 2 mask words per 64-key chunk (broadcast loads)
        uint32_t mw0 = g_pbits[b * 16 + kc * 2];
        uint32_t mw1 = g_pbits[b * 16 + kc * 2 + 1];

        if (kc + 1 < SS / KCH) {
            int nb = (kc + 1) & 1;
            cp16(ksd[nb], Kgh + (size_t)((kc + 1) * KCH + krow) * DHD + kcol);
            cp16(vsd[nb], Vgh + (size_t)vd * SS + (kc + 1) * KCH + vcol);
            asm volatile("cp.async.commit_group;\n");
            asm volatile("cp.async.wait_group 1;\n");
        } else {
            asm volatile("cp.async.wait_group 0;\n");
        }
        __syncthreads();

        float s[8][4];
        #pragma unroll
        for (int nt = 0; nt < 8; nt++)
            #pragma unroll
            for (int j = 0; j < 4; j++) s[nt][j] = 0.f;

        #pragma unroll
        for (int ks = 0; ks < 2; ks++) {
            int row = w * 16 + g, col = ks * 16 + 2 * T;
            uint32_t a0 = *(const uint32_t*)(Qs + row * QH + col);
            uint32_t a1 = *(const uint32_t*)(Qs + (row + 8) * QH + col);
            uint32_t a2 = *(const uint32_t*)(Qs + row * QH + col + 8);
            uint32_t a3 = *(const uint32_t*)(Qs + (row + 8) * QH + col + 8);
            #pragma unroll
            for (int nt = 0; nt < 8; nt++) {
                int kr = nt * 8 + g;
                uint32_t b0 = *(const uint32_t*)(&Ks[buf][kr * QH + col]);
                uint32_t b1 = *(const uint32_t*)(&Ks[buf][kr * QH + col + 8]);
                mma_f16(s[nt], a0, a1, a2, a3, b0, b1);
            }
        }

        // masking via bit-packed pads; word (nt>>2) is compile-time selectable
        #pragma unroll
        for (int nt = 0; nt < 8; nt++) {
            uint32_t wbits = (nt < 4) ? mw0 : mw1;
            int bit0 = (nt & 3) * 8 + 2 * T;
            if ((wbits >> bit0) & 1)       { s[nt][0] = -1e9f; s[nt][2] = -1e9f; }
            if ((wbits >> (bit0 + 1)) & 1) { s[nt][1] = -1e9f; s[nt][3] = -1e9f; }
        }

        #pragma unroll
        for (int half = 0; half < 2; half++) {
            float cmax = -1e30f;
            #pragma unroll
            for (int nt = 0; nt < 8; nt++)
                cmax = fmaxf(cmax, fmaxf(s[nt][2 * half], s[nt][2 * half + 1]));
            cmax = fmaxf(cmax, __shfl_xor_sync(0xffffffffu, cmax, 1));
            cmax = fmaxf(cmax, __shfl_xor_sync(0xffffffffu, cmax, 2));
            float mnew  = fmaxf(m_[half], cmax);
            float scale = fexp(m_[half] - mnew);
            m_[half] = mnew;
            float part = 0.f;
            #pragma unroll
            for (int nt = 0; nt < 8; nt++) {
                float p0 = fexp(s[nt][2 * half]     - mnew);
                float p1 = fexp(s[nt][2 * half + 1] - mnew);
                s[nt][2 * half] = p0; s[nt][2 * half + 1] = p1;
                part += p0 + p1;
            }
            part += __shfl_xor_sync(0xffffffffu, part, 1);
            part += __shfl_xor_sync(0xffffffffu, part, 2);
            sum_[half] = sum_[half] * scale + part;
            #pragma unroll
            for (int nt = 0; nt < 4; nt++) {
                o[nt][2 * half]     *= scale;
                o[nt][2 * half + 1] *= scale;
            }
        }

        #pragma unroll
        for (int kt = 0; kt < 4; kt++) {
            uint32_t a0 = packh2(s[2 * kt][0],     s[2 * kt][1]);
            uint32_t a1 = packh2(s[2 * kt][2],     s[2 * kt][3]);
            uint32_t a2 = packh2(s[2 * kt + 1][0], s[2 * kt + 1][1]);
            uint32_t a3 = packh2(s[2 * kt + 1][2], s[2 * kt + 1][3]);
            #pragma unroll
            for (int nt = 0; nt < 4; nt++) {
                const __half* vp = &Vts[buf][(nt * 8 + g) * VSTR + kt * 16 + 2 * T];
                uint32_t b0 = *(const uint32_t*)vp;
                uint32_t b1 = *(const uint32_t*)(vp + 8);
                mma_f16(o[nt], a0, a1, a2, a3, b0, b1);
            }
        }
        __syncthreads();
    }

    float i0 = 1.0f / sum_[0];
    float i1 = 1.0f / sum_[1];
    int q0 = qt * QTILE + w * 16 + g;
    #pragma unroll
    for (int nt = 0; nt < 4; nt++) {
        int col = h * DHD + nt * 8 + 2 * T;
        *(uint32_t*)(g_ctxh + (size_t)(b * SS + q0) * DD + col) =
            packh2(o[nt][0] * i0, o[nt][1] * i0);
        *(uint32_t*)(g_ctxh + (size_t)(b * SS + q0 + 8) * DD + col) =
            packh2(o[nt][2] * i1, o[nt][3] * i1);
    }
}

// ---------------- fused residual + LN (+optional gate) -----------------------
__device__ __forceinline__ void warp_add_ln(
    int n, int lane, const float* __restrict__ add,
    const float* __restrict__ gamma, const float* __restrict__ beta,
    float out[8])
{
    size_t base = (size_t)n * DD + lane;
    float v[8];
    float sum = 0.f;
    #pragma unroll
    for (int j = 0; j < 8; j++) {
        v[j] = g_h[base + 32 * j] + add[base + 32 * j];
        sum += v[j];
    }
    #pragma unroll
    for (int o = 16; o > 0; o >>= 1) sum += __shfl_xor_sync(0xffffffffu, sum, o);
    float mu = sum * (1.0f / DD);
    float sq = 0.f;
    #pragma unroll
    for (int j = 0; j < 8; j++) {
        v[j] -= mu;
        sq += v[j] * v[j];
    }
    #pragma unroll
    for (int o = 16; o > 0; o >>= 1) sq += __shfl_xor_sync(0xffffffffu, sq, o);
    float r = rsqrtf(sq * (1.0f / DD) + 1e-5f);
    #pragma unroll
    for (int j = 0; j < 8; j++) {
        out[j] = v[j] * r * gamma[lane + 32 * j] + beta[lane + 32 * j];
        g_h [base + 32 * j] = out[j];
        g_hh[base + 32 * j] = __float2half(out[j]);
    }
}

__global__ void add_ln2_kernel(const float* __restrict__ add,
                               const float* __restrict__ gamma,
                               const float* __restrict__ beta)
{
    int lane = threadIdx.x & 31;
    int n = blockIdx.x * 8 + (threadIdx.x >> 5);
    float out[8];
    warp_add_ln(n, lane, add, gamma, beta, out);
}

__global__ void add_ln1_gate_kernel(const float* __restrict__ add,
                                    const float* __restrict__ gamma,
                                    const float* __restrict__ beta,
                                    const float* __restrict__ gw,
                                    const float* __restrict__ gb,
                                    int* __restrict__ cnt_l)
{
    int lane = threadIdx.x & 31;
    int n = blockIdx.x * 8 + (threadIdx.x >> 5);
    float out[8];
    warp_add_ln(n, lane, add, gamma, beta, out);

    float lg[NEXP];
    #pragma unroll
    for (int e = 0; e < NEXP; e++) {
        float p = 0.f;
        #pragma unroll
        for (int j = 0; j < 8; j++)
            p = fmaf(gw[e * DD + lane + 32 * j], out[j], p);
        #pragma unroll
        for (int o = 16; o > 0; o >>= 1)
            p += __shfl_xor_sync(0xffffffffu, p, o);
        lg[e] = p;
    }
    if (lane == 0) {
        float m = -1e30f;
        #pragma unroll
        for (int i = 0; i < NEXP; i++) { lg[i] += gb[i]; m = fmaxf(m, lg[i]); }
        float p[NEXP], sum = 0.f;
        #pragma unroll
        for (int i = 0; i < NEXP; i++) { p[i] = expf(lg[i] - m); sum += p[i]; }
        int bi = 0; float bw = p[0];
        #pragma unroll
        for (int i = 1; i < NEXP; i++) if (p[i] > bw) { bw = p[i]; bi = i; }
        g_eidx[n] = bi;
        g_ew[n]   = bw / sum;
        atomicAdd(&cnt_l[bi], 1);
    }
}

// ---------------- routing bookkeeping (prefix + tile table) ------------------
__global__ void prefix_kernel(const int* __restrict__ cnt_l)
{
    if (threadIdx.x == 0) {
        int acc = 0, idx = 0;
        #pragma unroll
        for (int e = 0; e < NEXP; e++) {
            g_base[e] = acc; g_cursor[e] = acc;
            int c = cnt_l[e];
            acc += c;
            int nt = (c + 127) >> 7;
            for (int t = 0; t < nt; t++) g_tiletab[idx++] = (e << 16) | t;
        }
        g_ntiles = idx;
    }
}

__global__ void scatter_kernel()
{
    int n = blockIdx.x * blockDim.x + threadIdx.x;
    if (n < NTOK) {
        int e = g_eidx[n];
        int pos = atomicAdd(&g_cursor[e], 1);
        g_perm[pos] = n;
    }
}

// ---------------- head: partial pooling + final ------------------------------
__global__ void pool_kernel()
{
    int b = blockIdx.x, c = blockIdx.y;
    int tid = threadIdx.x;
    int base = b * SS + c * 64;
    float s = 0.f;
    #pragma unroll 8
    for (int i = 0; i < 64; i++) {
        int n = base + i;
        if (!g_pad[n]) s += g_h[(size_t)n * DD + tid];
    }
    g_pool[(b * 8 + c) * DD + tid] = s;
    if (tid == 0) {
        int t = 0;
        #pragma unroll 8
        for (int i = 0; i < 64; i++) t += (g_pad[base + i] == 0);
        g_pcnt[b * 8 + c] = t;
    }
}

__global__ void head_final(const float* __restrict__ fc1w, const float* __restrict__ fc1b,
                           const float* __restrict__ fc2w, const float* __restrict__ fc2b,
                           float* __restrict__ out)
{
    int b = blockIdx.x, tid = threadIdx.x;
    __shared__ float pooled[DD];
    __shared__ float z[128];
    __shared__ int scnt;

    float s = 0.f;
    #pragma unroll
    for (int c = 0; c < 8; c++) s += g_pool[(b * 8 + c) * DD + tid];
    if (tid == 0) {
        int t = 0;
        #pragma unroll
        for (int c = 0; c < 8; c++) t += g_pcnt[b * 8 + c];
        scnt = t;
    }
    __syncthreads();
    pooled[tid] = s / fmaxf((float)scnt, 1.0f);
    __syncthreads();

    if (tid < 128) {
        float a = fc1b[tid];
        const float* wr = fc1w + (size_t)tid * DD;
        #pragma unroll 8
        for (int d = 0; d < DD; d++) a += pooled[d] * wr[d];
        z[tid] = fmaxf(a, 0.f);
    }
    __syncthreads();
    if (tid < 2) {
        float a = fc2b[tid];
        const float* wr = fc2w + (size_t)tid * 128;
        #pragma unroll 8
        for (int i = 0; i < 128; i++) a += z[i] * wr[i];
        out[b * 2 + tid] = a;
    }
}

// ---------------- host launch ------------------------------------------------
static void* sym_addr(const void* sym)
{
    void* p = nullptr;
    cudaGetSymbolAddress(&p, sym);
    return p;
}

extern "C" void kernel_launch(void* const* d_in, const int* in_sizes, int n_in,
                              void* d_out, int out_size)
{
    const int*   x          = (const int*)  d_in[0];
    const float* emb        = (const float*)d_in[1];
    const float* in_proj_w  = (const float*)d_in[2];
    const float* in_proj_b  = (const float*)d_in[3];
    const float* out_proj_w = (const float*)d_in[4];
    const float* out_proj_b = (const float*)d_in[5];
    const float* ln1_g      = (const float*)d_in[6];
    const float* ln1_b      = (const float*)d_in[7];
    const float* ln2_g      = (const float*)d_in[8];
    const float* ln2_b      = (const float*)d_in[9];
    const float* gate_w     = (const float*)d_in[10];
    const float* gate_b     = (const float*)d_in[11];
    const float* w1         = (const float*)d_in[12];
    const float* b1         = (const float*)d_in[13];
    const float* w2         = (const float*)d_in[14];
    const float* b2         = (const float*)d_in[15];
    const float* fc1_w      = (const float*)d_in[16];
    const float* fc1_b      = (const float*)d_in[17];
    const float* fc2_w      = (const float*)d_in[18];
    const float* fc2_b      = (const float*)d_in[19];
    float* out = (float*)d_out;

    __half* wh    = (__half*)sym_addr(g_wh);
    __half* hh    = (__half*)sym_addr(g_hh);
    __half* ctxh  = (__half*)sym_addr(g_ctxh);
    float*  p_tmp = (float*)sym_addr(g_tmp);
    int*    cnt   = (int*)sym_addr(g_cnt);

    pe_kernel<<<DD, SS>>>();
    embed_kernel<<<NTOK/8, 256>>>(x, emb);
    pack_pad_kernel<<<8, 1024>>>();
    f2h_all<<<(WH_TOTAL/4 + 255)/256, 256>>>(in_proj_w, out_proj_w, w1, w2);

    for (int l = 0; l < NLAY; l++) {
        int* cnt_l = cnt + l * NEXP;

        gemm_qkv16<<<dim3(3*DD/128, NTOK/128), 256>>>(
            hh, wh + IPH_OFF + (size_t)l * 3*DD*DD, in_proj_b + (size_t)l * 3*DD);

        attn_fa_kernel<<<dim3(SS/QTILE, HH, BB), 256>>>();

        gemm_out16<<<dim3(DD/128, NTOK/128), 256>>>(
            ctxh, wh + OPH_OFF + (size_t)l * DD*DD, out_proj_b + (size_t)l * DD,
            p_tmp, DD, DD);

        add_ln1_gate_kernel<<<NTOK/8, 256>>>(
            p_tmp, ln1_g + (size_t)l * DD, ln1_b + (size_t)l * DD,
            gate_w + (size_t)l * NEXP*DD, gate_b + (size_t)l * NEXP, cnt_l);
        prefix_kernel<<<1, 32>>>(cnt_l);
        scatter_kernel<<<NTOK/256, 256>>>();

        moe_gemm1_16<<<dim3(EHID/128, 71), 256>>>(
            wh + W1H_OFF + (size_t)l * NEXP*EHID*DD, b1 + (size_t)l * NEXP*EHID, cnt_l);
        moe_gemm2_16<<<dim3(DD/128, 71), 256>>>(
            wh + W2H_OFF + (size_t)l * NEXP*DD*EHID, b2 + (size_t)l * NEXP*DD, cnt_l);

        add_ln2_kernel<<<NTOK/8, 256>>>(
            p_tmp, ln2_g + (size_t)l * DD, ln2_b + (size_t)l * DD);
    }

    pool_kernel<<<dim3(BB, 8), 256>>>();
    head_final<<<BB, 256>>>(fc1_w, fc1_b, fc2_w, fc2_b, out);
}

// round 16
// speedup vs baseline: 1.5543x; 1.0279x over previous
#include <cuda_runtime.h>
#include <cuda_fp16.h>
#include <math.h>
#include <stdint.h>

// ---------------- model dims ----------------
#define BB    16
#define SS    512
#define DD    256
#define HH    8
#define DHD   32
#define NLAY  2
#define NEXP  8
#define EHID  1024
#define NTOK  (BB*SS)   // 8192

// ---------------- scratch (static device globals) ---------------------------
__device__ float  g_h   [NTOK*DD];
__device__ __half g_hh  [NTOK*DD];
__device__ __half g_qh  [NTOK*DD];     // Q fp16, pre-scaled, [B][H][S][32]
__device__ __half g_kh  [NTOK*DD];     // K fp16, [B][H][S][32]
__device__ __half g_vth [NTOK*DD];     // V fp16 transposed, [B][H][32][S]
__device__ __half g_ctxh[NTOK*DD];
__device__ float  g_tmp [NTOK*DD];
__device__ __half g_h1h [NTOK*EHID];   // MoE hidden (fp16, indexed by TOKEN id)
__device__ float  g_pe  [SS*DD];
__device__ int    g_pad [NTOK];
__device__ uint32_t g_pbits[NTOK/32];
__device__ float  g_ew  [NTOK];
__device__ int    g_cnt [NLAY*NEXP];
__device__ int    g_perm[NEXP*NTOK];   // fixed expert stride NTOK
__device__ float  g_pool[BB*8*DD];
__device__ int    g_pcnt[BB*8];

// fp16 weight buffer (converted once per launch)
#define IPH_OFF 0
#define IPH_SZ  (NLAY*3*DD*DD)
#define OPH_OFF (IPH_OFF + IPH_SZ)
#define OPH_SZ  (NLAY*DD*DD)
#define W1H_OFF (OPH_OFF + OPH_SZ)
#define W1H_SZ  (NLAY*NEXP*EHID*DD)
#define W2H_OFF (W1H_OFF + W1H_SZ)
#define W2H_SZ  (NLAY*NEXP*DD*EHID)
#define WH_TOTAL (W2H_OFF + W2H_SZ)
__device__ __half g_wh[WH_TOTAL];

// ---------------- helpers ----------------------------------------------------
__device__ __forceinline__ void mma_f16(float* d, uint32_t a0, uint32_t a1,
                                        uint32_t a2, uint32_t a3,
                                        uint32_t b0, uint32_t b1)
{
    asm volatile(
        "mma.sync.aligned.m16n8k16.row.col.f32.f16.f16.f32 "
        "{%0,%1,%2,%3}, {%4,%5,%6,%7}, {%8,%9}, {%0,%1,%2,%3};\n"
        : "+f"(d[0]), "+f"(d[1]), "+f"(d[2]), "+f"(d[3])
        : "r"(a0), "r"(a1), "r"(a2), "r"(a3), "r"(b0), "r"(b1));
}

__device__ __forceinline__ void ldm_x4(uint32_t& r0, uint32_t& r1,
                                       uint32_t& r2, uint32_t& r3, uint32_t addr)
{
    asm volatile("ldmatrix.sync.aligned.m8n8.x4.shared.b16 {%0,%1,%2,%3}, [%4];"
                 : "=r"(r0), "=r"(r1), "=r"(r2), "=r"(r3) : "r"(addr));
}

__device__ __forceinline__ float fexp(float x)
{
    x = fmaxf(x, -87.0f);
    const float L2E = 1.4426950408889634f;
    float t  = fmaf(x, L2E, 12582912.0f);
    int   ki = __float_as_int(t) - 0x4B400000;
    float kf = t - 12582912.0f;
    float r  = fmaf(x, L2E, -kf);
    float p  = 1.3333558146e-3f;
    p = fmaf(p, r, 9.6181291076e-3f);
    p = fmaf(p, r, 5.5504108664e-2f);
    p = fmaf(p, r, 2.4022650696e-1f);
    p = fmaf(p, r, 6.9314718056e-1f);
    p = fmaf(p, r, 1.0f);
    return p * __int_as_float((ki + 127) << 23);
}

__device__ __forceinline__ uint32_t packh2(float a, float b)
{
    __half2 h = __floats2half2_rn(a, b);
    return *(uint32_t*)&h;
}

__device__ __forceinline__ void cp16(uint32_t dst, const void* src)
{
    asm volatile("cp.async.ca.shared.global [%0], [%1], 16;\n"
                 :: "r"(dst), "l"(src));
}

// inline (expert, tile) resolution from blockIdx.y by scanning counts
__device__ __forceinline__ bool resolve_tile(const int* cnt_l, int y,
                                             int& e, int& tile, int& cnt)
{
    int acc = 0;
    bool found = false;
    #pragma unroll
    for (int ee = 0; ee < NEXP; ee++) {
        int c  = cnt_l[ee];
        int nt = (c + 127) >> 7;
        if (!found && y < acc + nt) {
            e = ee; tile = y - acc; cnt = c; found = true;
        }
        acc += nt;
    }
    return found;
}

// ---------------- fp16 pipelined 128x128 GEMM core, BK=32 --------------------
#define H2STR 40
#define H2BUF (128 * H2STR)

__device__ __forceinline__ void pipe16_mainloop(
    const __half* __restrict__ aptr,
    const __half* __restrict__ wptr,
    int K, __half* AsArr, __half* BsArr, float acc[4][4][4])
{
    int tid = threadIdx.x, lane = tid & 31, w = tid >> 5;
    int wm = w & 1, wn = w >> 1;
    int row = tid >> 1, seg = (tid & 1) * 16;

    uint32_t aBase = (uint32_t)__cvta_generic_to_shared(AsArr);
    uint32_t bBase = (uint32_t)__cvta_generic_to_shared(BsArr);
    uint32_t da = aBase + (row * H2STR + seg) * 2;
    uint32_t db = bBase + (row * H2STR + seg) * 2;
    const uint32_t BUFB = H2BUF * 2;

    int l7 = lane & 7, lg1 = (lane >> 3) & 1, lg2 = (lane >> 4) & 1;
    uint32_t offA[4], offB[2];
    #pragma unroll
    for (int mt = 0; mt < 4; mt++) {
        int ar = wm * 64 + mt * 16 + l7 + lg1 * 8;
        offA[mt] = aBase + (ar * H2STR + lg2 * 8) * 2;
    }
    #pragma unroll
    for (int p = 0; p < 2; p++) {
        int br = wn * 32 + (2 * p + lg2) * 8 + l7;
        offB[p] = bBase + (br * H2STR + lg1 * 8) * 2;
    }

    int KT = K / 32;

    cp16(da,      aptr);     cp16(da + 16, aptr + 8);
    cp16(db,      wptr);     cp16(db + 16, wptr + 8);
    asm volatile("cp.async.commit_group;\n");

    for (int kt = 0; kt < KT; kt++) {
        if (kt + 1 < KT) {
            uint32_t off = ((kt + 1) & 1) * BUFB;
            const __half* as = aptr + (kt + 1) * 32;
            const __half* ws = wptr + (kt + 1) * 32;
            cp16(da + off,      as);     cp16(da + off + 16, as + 8);
            cp16(db + off,      ws);     cp16(db + off + 16, ws + 8);
            asm volatile("cp.async.commit_group;\n");
            asm volatile("cp.async.wait_group 1;\n");
        } else {
            asm volatile("cp.async.wait_group 0;\n");
        }
        __syncthreads();

        uint32_t so = (kt & 1) * BUFB;

        #pragma unroll
        for (int kh = 0; kh < 2; kh++) {
            uint32_t ko = so + kh * 32;
            uint32_t afr[4][4], bfr[4][2];
            #pragma unroll
            for (int mt = 0; mt < 4; mt++)
                ldm_x4(afr[mt][0], afr[mt][1], afr[mt][2], afr[mt][3], offA[mt] + ko);
            ldm_x4(bfr[0][0], bfr[0][1], bfr[1][0], bfr[1][1], offB[0] + ko);
            ldm_x4(bfr[2][0], bfr[2][1], bfr[3][0], bfr[3][1], offB[1] + ko);

            #pragma unroll
            for (int mt = 0; mt < 4; mt++)
                #pragma unroll
                for (int nt = 0; nt < 4; nt++)
                    mma_f16(acc[mt][nt], afr[mt][0], afr[mt][1], afr[mt][2], afr[mt][3],
                            bfr[nt][0], bfr[nt][1]);
        }
        __syncthreads();
    }
}

// ---------------- fused weight conversion (fp32 -> fp16, 32B/thread) ---------
__global__ void f2h_all(const float* __restrict__ s0, const float* __restrict__ s1,
                        const float* __restrict__ s2, const float* __restrict__ s3)
{
    int u = blockIdx.x * 256 + threadIdx.x;   // 8-float unit
    if (u >= WH_TOTAL / 8) return;
    #pragma unroll
    for (int p = 0; p < 2; p++) {
        int i = 2 * u + p;                     // 4-float unit
        const float* src;
        int local;
        if (i < IPH_SZ / 4)                        { src = s0; local = i; }
        else if (i < (IPH_SZ + OPH_SZ) / 4)        { src = s1; local = i - IPH_SZ / 4; }
        else if (i < (IPH_SZ + OPH_SZ + W1H_SZ)/4) { src = s2; local = i - (IPH_SZ + OPH_SZ) / 4; }
        else                                       { src = s3; local = i - (IPH_SZ + OPH_SZ + W1H_SZ) / 4; }
        float4 v = ((const float4*)src)[local];
        ((__half2*)g_wh)[2 * i + 0] = __floats2half2_rn(v.x, v.y);
        ((__half2*)g_wh)[2 * i + 1] = __floats2half2_rn(v.z, v.w);
    }
}

// ---------------- positional encoding (cheap FP64) + cnt zeroing -------------
__global__ void pe_kernel()
{
    int d = blockIdx.x, s = threadIdx.x;
    if (blockIdx.x == 0 && threadIdx.x < NLAY * NEXP) g_cnt[threadIdx.x] = 0;
    __shared__ double freq_sh;
    if (threadIdx.x == 0)
        freq_sh = exp(-(double)(d & ~1) * (log(10000.0) / (double)DD));
    __syncthreads();
    double arg = (double)s * freq_sh;
    const double TWOPI = 6.283185307179586476925286766559;
    double r = arg - TWOPI * rint(arg * (1.0 / TWOPI));
    float rf = (float)r;
    g_pe[s * DD + d] = (d & 1) ? cosf(rf) : sinf(rf);
}

// ---------------- embedding + pad mask (warp per token) ----------------------
__global__ void embed_kernel(const int* __restrict__ x, const float* __restrict__ emb)
{
    int lane = threadIdx.x & 31;
    int n = blockIdx.x * 8 + (threadIdx.x >> 5);
    int tok = x[n];
    int s = n & (SS - 1);

    const float* er = emb + (size_t)tok * DD;
    const float* pr = g_pe + s * DD;
    size_t base = (size_t)n * DD;

    float v[8];
    float sum = 0.f;
    #pragma unroll
    for (int j = 0; j < 8; j++) {
        int d = lane + 32 * j;
        v[j] = er[d] * 16.0f + pr[d];
        sum += v[j];
        g_h [base + d] = v[j];
        g_hh[base + d] = __float2half(v[j]);
    }
    #pragma unroll
    for (int o = 16; o > 0; o >>= 1) sum += __shfl_xor_sync(0xffffffffu, sum, o);
    if (lane == 0) g_pad[n] = (sum == 0.0f) ? 1 : 0;
}

// ---------------- pack pad bits (warp per 32 tokens) -------------------------
__global__ void pack_pad_kernel()
{
    int wi = blockIdx.x * 32 + (threadIdx.x >> 5);
    int lane = threadIdx.x & 31;
    uint32_t bal = __ballot_sync(0xffffffffu, g_pad[wi * 32 + lane] != 0);
    if (lane == 0) g_pbits[wi] = bal;
}

// ---------------- QKV GEMM (fp16) + fp16 split store -------------------------
__global__ __launch_bounds__(256)
void gemm_qkv16(const __half* __restrict__ A,
                const __half* __restrict__ W,
                const float* __restrict__ bias)
{
    __shared__ __align__(16) __half As[2 * H2BUF];
    __shared__ __align__(16) __half Bs[2 * H2BUF];

    int tid = threadIdx.x, lane = tid & 31, w = tid >> 5;
    int wm = w & 1, wn = w >> 1, g = lane >> 2, T = lane & 3;
    int m0 = blockIdx.y * 128, n0 = blockIdx.x * 128;
    int row = tid >> 1, seg = (tid & 1) * 16;

    const float inv = 0.17677669529663689f;

    float acc[4][4][4] = {};
    pipe16_mainloop(A + (size_t)(m0 + row) * DD + seg,
                    W + (size_t)(n0 + row) * DD + seg, DD, As, Bs, acc);

    #pragma unroll
    for (int mt = 0; mt < 4; mt++) {
        #pragma unroll
        for (int nt = 0; nt < 4; nt++) {
            int r0 = m0 + wm * 64 + mt * 16 + g;
            int c0 = n0 + wn * 32 + nt * 8 + 2 * T;
            int t = c0 >> 8, h = (c0 >> 5) & 7, d = c0 & 31;
            float bx = bias[c0], by = bias[c0 + 1];
            #pragma unroll
            for (int half = 0; half < 2; half++) {
                int rr = r0 + half * 8;
                int b = rr >> 9, s = rr & (SS - 1);
                int bh = b * HH + h;
                float v0 = acc[mt][nt][half * 2 + 0] + bx;
                float v1 = acc[mt][nt][half * 2 + 1] + by;
                if (t == 0) {
                    *(uint32_t*)(g_qh + ((size_t)(bh * SS + s)) * DHD + d) =
                        packh2(v0 * inv, v1 * inv);
                } else if (t == 1) {
                    *(uint32_t*)(g_kh + ((size_t)(bh * SS + s)) * DHD + d) =
                        packh2(v0, v1);
                } else {
                    g_vth[((size_t)(bh * DHD + d    )) * SS + s] = __float2half(v0);
                    g_vth[((size_t)(bh * DHD + d + 1)) * SS + s] = __float2half(v1);
                }
            }
        }
    }
}

// ---------------- out-proj GEMM (fp16) ---------------------------------------
__global__ __launch_bounds__(256)
void gemm_out16(const __half* __restrict__ A,
                const __half* __restrict__ W,
                const float* __restrict__ bias,
                float* __restrict__ C, int Nc, int K)
{
    __shared__ __align__(16) __half As[2 * H2BUF];
    __shared__ __align__(16) __half Bs[2 * H2BUF];

    int tid = threadIdx.x, lane = tid & 31, w = tid >> 5;
    int wm = w & 1, wn = w >> 1, g = lane >> 2, T = lane & 3;
    int m0 = blockIdx.y * 128, n0 = blockIdx.x * 128;
    int row = tid >> 1, seg = (tid & 1) * 16;

    float acc[4][4][4] = {};
    pipe16_mainloop(A + (size_t)(m0 + row) * K + seg,
                    W + (size_t)(n0 + row) * K + seg, K, As, Bs, acc);

    #pragma unroll
    for (int mt = 0; mt < 4; mt++) {
        #pragma unroll
        for (int nt = 0; nt < 4; nt++) {
            int r0 = m0 + wm * 64 + mt * 16 + g;
            int c0 = n0 + wn * 32 + nt * 8 + 2 * T;
            float bx = bias[c0], by = bias[c0 + 1];
            #pragma unroll
            for (int half = 0; half < 2; half++) {
                int rr = r0 + half * 8;
                float2 v = make_float2(acc[mt][nt][half * 2 + 0] + bx,
                                       acc[mt][nt][half * 2 + 1] + by);
                *(float2*)(C + (size_t)rr * Nc + c0) = v;
            }
        }
    }
}

// ---------------- MoE GEMM1 (fp16, inline tile resolve) ----------------------
__global__ __launch_bounds__(256)
void moe_gemm1_16(const __half* __restrict__ w1, const float* __restrict__ b1,
                  const int* __restrict__ cnt_l)
{
    int e, tile, cnt;
    if (!resolve_tile(cnt_l, blockIdx.y, e, tile, cnt)) return;

    __shared__ __align__(16) __half As[2 * H2BUF];
    __shared__ __align__(16) __half Bs[2 * H2BUF];

    int tid = threadIdx.x, lane = tid & 31, w = tid >> 5;
    int wm = w & 1, wn = w >> 1, g = lane >> 2, T = lane & 3;
    int n0 = blockIdx.x * 128;
    int row = tid >> 1, seg = (tid & 1) * 16;

    int gr = tile * 128 + row;
    if (gr >= cnt) gr = cnt - 1;
    int token = g_perm[e * NTOK + gr];

    float acc[4][4][4] = {};
    pipe16_mainloop(g_hh + (size_t)token * DD + seg,
                    w1 + (size_t)e * EHID * DD + (size_t)(n0 + row) * DD + seg,
                    DD, As, Bs, acc);

    #pragma unroll
    for (int mt = 0; mt < 4; mt++) {
        #pragma unroll
        for (int nt = 0; nt < 4; nt++) {
            int lr0 = wm * 64 + mt * 16 + g;
            int c0  = n0 + wn * 32 + nt * 8 + 2 * T;
            float bx = b1[e * EHID + c0], by = b1[e * EHID + c0 + 1];
            #pragma unroll
            for (int half = 0; half < 2; half++) {
                int grr = tile * 128 + lr0 + half * 8;
                if (grr < cnt) {
                    int tko = g_perm[e * NTOK + grr];
                    float v0 = fmaxf(acc[mt][nt][half * 2 + 0] + bx, 0.f);
                    float v1 = fmaxf(acc[mt][nt][half * 2 + 1] + by, 0.f);
                    *(uint32_t*)(g_h1h + (size_t)tko * EHID + c0) = packh2(v0, v1);
                }
            }
        }
    }
}

// ---------------- MoE GEMM2 (fp16, inline tile resolve) ----------------------
__global__ __launch_bounds__(256)
void moe_gemm2_16(const __half* __restrict__ w2, const float* __restrict__ b2,
                  const int* __restrict__ cnt_l)
{
    int e, tile, cnt;
    if (!resolve_tile(cnt_l, blockIdx.y, e, tile, cnt)) return;

    __shared__ __align__(16) __half As[2 * H2BUF];
    __shared__ __align__(16) __half Bs[2 * H2BUF];

    int tid = threadIdx.x, lane = tid & 31, w = tid >> 5;
    int wm = w & 1, wn = w >> 1, g = lane >> 2, T = lane & 3;
    int n0 = blockIdx.x * 128;
    int row = tid >> 1, seg = (tid & 1) * 16;

    int gr = tile * 128 + row;
    if (gr >= cnt) gr = cnt - 1;
    int token = g_perm[e * NTOK + gr];

    float acc[4][4][4] = {};
    pipe16_mainloop(g_h1h + (size_t)token * EHID + seg,
                    w2 + (size_t)e * DD * EHID + (size_t)(n0 + row) * EHID + seg,
                    EHID, As, Bs, acc);

    #pragma unroll
    for (int mt = 0; mt < 4; mt++) {
        #pragma unroll
        for (int nt = 0; nt < 4; nt++) {
            int lr0 = wm * 64 + mt * 16 + g;
            int c0  = n0 + wn * 32 + nt * 8 + 2 * T;
            float bx = b2[e * DD + c0], by = b2[e * DD + c0 + 1];
            #pragma unroll
            for (int half = 0; half < 2; half++) {
                int grr = tile * 128 + lr0 + half * 8;
                if (grr < cnt) {
                    int tko = g_perm[e * NTOK + grr];
                    float gwv = g_ew[tko];
                    float2 v = make_float2(gwv * (acc[mt][nt][half * 2 + 0] + bx),
                                           gwv * (acc[mt][nt][half * 2 + 1] + by));
                    *(float2*)(g_tmp + (size_t)tko * DD + c0) = v;
                }
            }
        }
    }
}

// ---------------- flash attention (fp16, KCH=64, bit-packed mask) ------------
#define QTILE 128
#define KCH   64
#define QH    40
#define VSTR  72

__global__ void attn_fa_kernel()
{
    __shared__ __align__(16) __half Qs [QTILE * QH];
    __shared__ __align__(16) __half Ks [2][KCH * QH];
    __shared__ __align__(16) __half Vts[2][DHD * VSTR];

    int qt = blockIdx.x, h = blockIdx.y, b = blockIdx.z;
    int tid = threadIdx.x, lane = tid & 31, w = tid >> 5;
    int g = lane >> 2, T = lane & 3;
    int bh = b * HH + h;

    const __half* Qgh = g_qh  + ((size_t)(bh * SS + qt * QTILE)) * DHD;
    const __half* Kgh = g_kh  + ((size_t)(bh * SS)) * DHD;
    const __half* Vgh = g_vth + ((size_t)bh * DHD) * SS;

    int krow = tid >> 2, kcol = (tid & 3) * 8;
    int vd   = tid >> 3, vcol = (tid & 7) * 8;
    uint32_t ksd[2], vsd[2];
    #pragma unroll
    for (int p = 0; p < 2; p++) {
        ksd[p] = (uint32_t)__cvta_generic_to_shared(&Ks[p][krow * QH + kcol]);
        vsd[p] = (uint32_t)__cvta_generic_to_shared(&Vts[p][vd * VSTR + vcol]);
    }

    for (int i = tid; i < 512; i += 256) {
        int row = i >> 2, c = (i & 3) * 8;
        *(uint4*)(Qs + row * QH + c) = *(const uint4*)(Qgh + row * DHD + c);
    }

    {
        cp16(ksd[0], Kgh + (size_t)krow * DHD + kcol);
        cp16(vsd[0], Vgh + (size_t)vd * SS + vcol);
        asm volatile("cp.async.commit_group;\n");
    }

    float m_[2]  = {-1e30f, -1e30f};
    float sum_[2] = {0.f, 0.f};
    float o[4][4] = {};

    for (int kc = 0; kc < SS / KCH; kc++) {
        int buf = kc & 1;
        uint32_t mw0 = g_pbits[b * 16 + kc * 2];
        uint32_t mw1 = g_pbits[b * 16 + kc * 2 + 1];

        if (kc + 1 < SS / KCH) {
            int nb = (kc + 1) & 1;
            cp16(ksd[nb], Kgh + (size_t)((kc + 1) * KCH + krow) * DHD + kcol);
            cp16(vsd[nb], Vgh + (size_t)vd * SS + (kc + 1) * KCH + vcol);
            asm volatile("cp.async.commit_group;\n");
            asm volatile("cp.async.wait_group 1;\n");
        } else {
            asm volatile("cp.async.wait_group 0;\n");
        }
        __syncthreads();

        float s[8][4];
        #pragma unroll
        for (int nt = 0; nt < 8; nt++)
            #pragma unroll
            for (int j = 0; j < 4; j++) s[nt][j] = 0.f;

        #pragma unroll
        for (int ks = 0; ks < 2; ks++) {
            int row = w * 16 + g, col = ks * 16 + 2 * T;
            uint32_t a0 = *(const uint32_t*)(Qs + row * QH + col);
            uint32_t a1 = *(const uint32_t*)(Qs + (row + 8) * QH + col);
            uint32_t a2 = *(const uint32_t*)(Qs + row * QH + col + 8);
            uint32_t a3 = *(const uint32_t*)(Qs + (row + 8) * QH + col + 8);
            #pragma unroll
            for (int nt = 0; nt < 8; nt++) {
                int kr = nt * 8 + g;
                uint32_t b0 = *(const uint32_t*)(&Ks[buf][kr * QH + col]);
                uint32_t b1 = *(const uint32_t*)(&Ks[buf][kr * QH + col + 8]);
                mma_f16(s[nt], a0, a1, a2, a3, b0, b1);
            }
        }

        #pragma unroll
        for (int nt = 0; nt < 8; nt++) {
            uint32_t wbits = (nt < 4) ? mw0 : mw1;
            int bit0 = (nt & 3) * 8 + 2 * T;
            if ((wbits >> bit0) & 1)       { s[nt][0] = -1e9f; s[nt][2] = -1e9f; }
            if ((wbits >> (bit0 + 1)) & 1) { s[nt][1] = -1e9f; s[nt][3] = -1e9f; }
        }

        #pragma unroll
        for (int half = 0; half < 2; half++) {
            float cmax = -1e30f;
            #pragma unroll
            for (int nt = 0; nt < 8; nt++)
                cmax = fmaxf(cmax, fmaxf(s[nt][2 * half], s[nt][2 * half + 1]));
            cmax = fmaxf(cmax, __shfl_xor_sync(0xffffffffu, cmax, 1));
            cmax = fmaxf(cmax, __shfl_xor_sync(0xffffffffu, cmax, 2));
            float mnew  = fmaxf(m_[half], cmax);
            float scale = fexp(m_[half] - mnew);
            m_[half] = mnew;
            float part = 0.f;
            #pragma unroll
            for (int nt = 0; nt < 8; nt++) {
                float p0 = fexp(s[nt][2 * half]     - mnew);
                float p1 = fexp(s[nt][2 * half + 1] - mnew);
                s[nt][2 * half] = p0; s[nt][2 * half + 1] = p1;
                part += p0 + p1;
            }
            part += __shfl_xor_sync(0xffffffffu, part, 1);
            part += __shfl_xor_sync(0xffffffffu, part, 2);
            sum_[half] = sum_[half] * scale + part;
            #pragma unroll
            for (int nt = 0; nt < 4; nt++) {
                o[nt][2 * half]     *= scale;
                o[nt][2 * half + 1] *= scale;
            }
        }

        #pragma unroll
        for (int kt = 0; kt < 4; kt++) {
            uint32_t a0 = packh2(s[2 * kt][0],     s[2 * kt][1]);
            uint32_t a1 = packh2(s[2 * kt][2],     s[2 * kt][3]);
            uint32_t a2 = packh2(s[2 * kt + 1][0], s[2 * kt + 1][1]);
            uint32_t a3 = packh2(s[2 * kt + 1][2], s[2 * kt + 1][3]);
            #pragma unroll
            for (int nt = 0; nt < 4; nt++) {
                const __half* vp = &Vts[buf][(nt * 8 + g) * VSTR + kt * 16 + 2 * T];
                uint32_t b0 = *(const uint32_t*)vp;
                uint32_t b1 = *(const uint32_t*)(vp + 8);
                mma_f16(o[nt], a0, a1, a2, a3, b0, b1);
            }
        }
        __syncthreads();
    }

    float i0 = 1.0f / sum_[0];
    float i1 = 1.0f / sum_[1];
    int q0 = qt * QTILE + w * 16 + g;
    #pragma unroll
    for (int nt = 0; nt < 4; nt++) {
        int col = h * DHD + nt * 8 + 2 * T;
        *(uint32_t*)(g_ctxh + (size_t)(b * SS + q0) * DD + col) =
            packh2(o[nt][0] * i0, o[nt][1] * i0);
        *(uint32_t*)(g_ctxh + (size_t)(b * SS + q0 + 8) * DD + col) =
            packh2(o[nt][2] * i1, o[nt][3] * i1);
    }
}

// ---------------- fused residual + LN (+optional gate with direct routing) ---
__device__ __forceinline__ void warp_add_ln(
    int n, int lane, const float* __restrict__ add,
    const float* __restrict__ gamma, const float* __restrict__ beta,
    float out[8])
{
    size_t base = (size_t)n * DD + lane;
    float v[8];
    float sum = 0.f;
    #pragma unroll
    for (int j = 0; j < 8; j++) {
        v[j] = g_h[base + 32 * j] + add[base + 32 * j];
        sum += v[j];
    }
    #pragma unroll
    for (int o = 16; o > 0; o >>= 1) sum += __shfl_xor_sync(0xffffffffu, sum, o);
    float mu = sum * (1.0f / DD);
    float sq = 0.f;
    #pragma unroll
    for (int j = 0; j < 8; j++) {
        v[j] -= mu;
        sq += v[j] * v[j];
    }
    #pragma unroll
    for (int o = 16; o > 0; o >>= 1) sq += __shfl_xor_sync(0xffffffffu, sq, o);
    float r = rsqrtf(sq * (1.0f / DD) + 1e-5f);
    #pragma unroll
    for (int j = 0; j < 8; j++) {
        out[j] = v[j] * r * gamma[lane + 32 * j] + beta[lane + 32 * j];
        g_h [base + 32 * j] = out[j];
        g_hh[base + 32 * j] = __float2half(out[j]);
    }
}

__global__ void add_ln2_kernel(const float* __restrict__ add,
                               const float* __restrict__ gamma,
                               const float* __restrict__ beta)
{
    int lane = threadIdx.x & 31;
    int n = blockIdx.x * 8 + (threadIdx.x >> 5);
    float out[8];
    warp_add_ln(n, lane, add, gamma, beta, out);
}

__global__ void add_ln1_gate_kernel(const float* __restrict__ add,
                                    const float* __restrict__ gamma,
                                    const float* __restrict__ beta,
                                    const float* __restrict__ gw,
                                    const float* __restrict__ gb,
                                    int* __restrict__ cnt_l)
{
    int lane = threadIdx.x & 31;
    int n = blockIdx.x * 8 + (threadIdx.x >> 5);
    float out[8];
    warp_add_ln(n, lane, add, gamma, beta, out);

    float lg[NEXP];
    #pragma unroll
    for (int e = 0; e < NEXP; e++) {
        float p = 0.f;
        #pragma unroll
        for (int j = 0; j < 8; j++)
            p = fmaf(gw[e * DD + lane + 32 * j], out[j], p);
        #pragma unroll
        for (int o = 16; o > 0; o >>= 1)
            p += __shfl_xor_sync(0xffffffffu, p, o);
        lg[e] = p;
    }
    if (lane == 0) {
        float m = -1e30f;
        #pragma unroll
        for (int i = 0; i < NEXP; i++) { lg[i] += gb[i]; m = fmaxf(m, lg[i]); }
        float p[NEXP], sum = 0.f;
        #pragma unroll
        for (int i = 0; i < NEXP; i++) { p[i] = expf(lg[i] - m); sum += p[i]; }
        int bi = 0; float bw = p[0];
        #pragma unroll
        for (int i = 1; i < NEXP; i++) if (p[i] > bw) { bw = p[i]; bi = i; }
        g_ew[n] = bw / sum;
        int pos = atomicAdd(&cnt_l[bi], 1);
        g_perm[bi * NTOK + pos] = n;       // direct slot claim, no scatter pass
    }
}

// ---------------- head: partial pooling + final ------------------------------
__global__ void pool_kernel()
{
    int b = blockIdx.x, c = blockIdx.y;
    int tid = threadIdx.x;
    int base = b * SS + c * 64;
    float s = 0.f;
    #pragma unroll 8
    for (int i = 0; i < 64; i++) {
        int n = base + i;
        if (!g_pad[n]) s += g_h[(size_t)n * DD + tid];
    }
    g_pool[(b * 8 + c) * DD + tid] = s;
    if (tid == 0) {
        int t = 0;
        #pragma unroll 8
        for (int i = 0; i < 64; i++) t += (g_pad[base + i] == 0);
        g_pcnt[b * 8 + c] = t;
    }
}

__global__ void head_final(const float* __restrict__ fc1w, const float* __restrict__ fc1b,
                           const float* __restrict__ fc2w, const float* __restrict__ fc2b,
                           float* __restrict__ out)
{
    int b = blockIdx.x, tid = threadIdx.x;
    __shared__ float pooled[DD];
    __shared__ float z[128];
    __shared__ int scnt;

    float s = 0.f;
    #pragma unroll
    for (int c = 0; c < 8; c++) s += g_pool[(b * 8 + c) * DD + tid];
    if (tid == 0) {
        int t = 0;
        #pragma unroll
        for (int c = 0; c < 8; c++) t += g_pcnt[b * 8 + c];
        scnt = t;
    }
    __syncthreads();
    pooled[tid] = s / fmaxf((float)scnt, 1.0f);
    __syncthreads();

    if (tid < 128) {
        float a = fc1b[tid];
        const float* wr = fc1w + (size_t)tid * DD;
        #pragma unroll 8
        for (int d = 0; d < DD; d++) a += pooled[d] * wr[d];
        z[tid] = fmaxf(a, 0.f);
    }
    __syncthreads();
    if (tid < 2) {
        float a = fc2b[tid];
        const float* wr = fc2w + (size_t)tid * 128;
        #pragma unroll 8
        for (int i = 0; i < 128; i++) a += z[i] * wr[i];
        out[b * 2 + tid] = a;
    }
}

// ---------------- host launch ------------------------------------------------
static void* sym_addr(const void* sym)
{
    void* p = nullptr;
    cudaGetSymbolAddress(&p, sym);
    return p;
}

extern "C" void kernel_launch(void* const* d_in, const int* in_sizes, int n_in,
                              void* d_out, int out_size)
{
    const int*   x          = (const int*)  d_in[0];
    const float* emb        = (const float*)d_in[1];
    const float* in_proj_w  = (const float*)d_in[2];
    const float* in_proj_b  = (const float*)d_in[3];
    const float* out_proj_w = (const float*)d_in[4];
    const float* out_proj_b = (const float*)d_in[5];
    const float* ln1_g      = (const float*)d_in[6];
    const float* ln1_b      = (const float*)d_in[7];
    const float* ln2_g      = (const float*)d_in[8];
    const float* ln2_b      = (const float*)d_in[9];
    const float* gate_w     = (const float*)d_in[10];
    const float* gate_b     = (const float*)d_in[11];
    const float* w1         = (const float*)d_in[12];
    const float* b1         = (const float*)d_in[13];
    const float* w2         = (const float*)d_in[14];
    const float* b2         = (const float*)d_in[15];
    const float* fc1_w      = (const float*)d_in[16];
    const float* fc1_b      = (const float*)d_in[17];
    const float* fc2_w      = (const float*)d_in[18];
    const float* fc2_b      = (const float*)d_in[19];
    float* out = (float*)d_out;

    __half* wh    = (__half*)sym_addr(g_wh);
    __half* hh    = (__half*)sym_addr(g_hh);
    __half* ctxh  = (__half*)sym_addr(g_ctxh);
    float*  p_tmp = (float*)sym_addr(g_tmp);
    int*    cnt   = (int*)sym_addr(g_cnt);

    pe_kernel<<<DD, SS>>>();
    embed_kernel<<<NTOK/8, 256>>>(x, emb);
    pack_pad_kernel<<<8, 1024>>>();
    f2h_all<<<(WH_TOTAL/8 + 255)/256, 256>>>(in_proj_w, out_proj_w, w1, w2);

    for (int l = 0; l < NLAY; l++) {
        int* cnt_l = cnt + l * NEXP;

        gemm_qkv16<<<dim3(3*DD/128, NTOK/128), 256>>>(
            hh, wh + IPH_OFF + (size_t)l * 3*DD*DD, in_proj_b + (size_t)l * 3*DD);

        attn_fa_kernel<<<dim3(SS/QTILE, HH, BB), 256>>>();

        gemm_out16<<<dim3(DD/128, NTOK/128), 256>>>(
            ctxh, wh + OPH_OFF + (size_t)l * DD*DD, out_proj_b + (size_t)l * DD,
            p_tmp, DD, DD);

        add_ln1_gate_kernel<<<NTOK/8, 256>>>(
            p_tmp, ln1_g + (size_t)l * DD, ln1_b + (size_t)l * DD,
            gate_w + (size_t)l * NEXP*DD, gate_b + (size_t)l * NEXP, cnt_l);

        moe_gemm1_16<<<dim3(EHID/128, 71), 256>>>(
            wh + W1H_OFF + (size_t)l * NEXP*EHID*DD, b1 + (size_t)l * NEXP*EHID, cnt_l);
        moe_gemm2_16<<<dim3(DD/128, 71), 256>>>(
            wh + W2H_OFF + (size_t)l * NEXP*DD*EHID, b2 + (size_t)l * NEXP*DD, cnt_l);

        add_ln2_kernel<<<NTOK/8, 256>>>(
            p_tmp, ln2_g + (size_t)l * DD, ln2_b + (size_t)l * DD);
    }

    pool_kernel<<<dim3(BB, 8), 256>>>();
    head_final<<<BB, 256>>>(fc1_w, fc1_b, fc2_w, fc2_b, out);
}